// round 2
// baseline (speedup 1.0000x reference)
#include <cuda_runtime.h>
#include <cfloat>

#define Nn 20000
#define Ee 320000
#define Gg 64
#define D0 16
#define Hh 32
#define NK 33
#define EPSI 1e-5f

// ---------------- static device scratch (no allocation allowed) ----------------
__device__ float g_t0[32], g_t1[32];
__device__ int   g_r0[32], g_r1[32];
__device__ float g_A0[NK*D0*Hh], g_B0[NK*D0*Hh];
__device__ float g_A1[NK*Hh*Hh], g_B1[NK*Hh*Hh];
__device__ unsigned char g_k0[Ee], g_k1[Ee];
__device__ int g_hist[2*NK];
__device__ int g_deg[Nn], g_off[Nn+1], g_cur[Nn], g_perm[Ee];
__device__ float g_P[NK*Nn*Hh], g_Q[NK*Nn*Hh];     // per-interval, per-node precompute
__device__ float g_h[Nn*Hh], g_hn[Nn*Hh];
__device__ float g_stats[2*Hh];
__device__ float g_pool[Gg*Hh];
__device__ int   g_pcnt[Gg];

// ---- thresholds + stable ranks for both layers (1 warp each) ----
__global__ void __launch_bounds__(64)
k_prep(const float* w0, const float* b0, const float* w1, const float* b1){
    int warp = threadIdx.x >> 5, j = threadIdx.x & 31;
    const float* W = warp ? w1 : w0;
    const float* B = warp ? b1 : b0;
    float wj = W[j], bj = B[j];
    float t = (wj != 0.0f) ? (-bj / wj) : FLT_MAX;
    int r = 0;
    for (int m = 0; m < 32; m++) {
        float tm = __shfl_sync(0xffffffffu, t, m);
        if (tm < t || (tm == t && m < j)) r++;
    }
    if (warp) { g_t1[j] = t; g_r1[j] = r; }
    else      { g_t0[j] = t; g_r0[j] = r; }
}

// ---- per-interval collapsed edge-MLP matrices: A_k, B_k ----
__global__ void __launch_bounds__(256)
k_buildAB(const float* ew1, const float* eb1, const float* ew2,
          const float* eb2, int layer){
    int D = layer ? (Hh*Hh) : (D0*Hh);
    float* A = layer ? g_A1 : g_A0;
    float* B = layer ? g_B1 : g_B0;
    const int* rk = layer ? g_r1 : g_r0;
    int k = blockIdx.x;
    __shared__ float sw[32], sb[32]; __shared__ int sr[32];
    if (threadIdx.x < 32){
        sw[threadIdx.x]=ew1[threadIdx.x]; sb[threadIdx.x]=eb1[threadIdx.x];
        sr[threadIdx.x]=rk[threadIdx.x];
    }
    __syncthreads();
    for (int d = threadIdx.x; d < D; d += blockDim.x){
        float a = 0.f, b = eb2[d];
        for (int j=0;j<32;j++){
            float wj = sw[j];
            bool act = (wj > 0.f) ? (k > sr[j]) : ((wj < 0.f) ? (k <= sr[j]) : (sb[j] > 0.f));
            if (act){ float w2 = ew2[j*D+d]; a += wj*w2; b += sb[j]*w2; }
        }
        A[k*D+d]=a; B[k*D+d]=b;
    }
}

// ---- per-edge interval index (both layers), interval histogram, dst-degree count ----
__global__ void __launch_bounds__(256)
k_edge(const float* attr, const int* dst){
    __shared__ float st0[32], st1[32];
    __shared__ int sh[2*NK];
    int t = threadIdx.x;
    if (t < 32) st0[t] = g_t0[t];
    else if (t < 64) st1[t-32] = g_t1[t-32];
    if (t < 2*NK) sh[t] = 0;
    __syncthreads();
    int e = blockIdx.x*blockDim.x + t;
    if (e < Ee){
        float a = attr[e];
        int k0=0,k1=0;
        #pragma unroll
        for (int j=0;j<32;j++){ k0 += (st0[j] <= a); k1 += (st1[j] <= a); }
        g_k0[e]=(unsigned char)k0; g_k1[e]=(unsigned char)k1;
        atomicAdd(&sh[k0],1); atomicAdd(&sh[NK+k1],1);
        atomicAdd(&g_deg[dst[e]],1);
    }
    __syncthreads();
    if (t < 2*NK && sh[t]) atomicAdd(&g_hist[t], sh[t]);
}

// ---- single-block exclusive scan of degrees -> CSR offsets ----
__global__ void __launch_bounds__(1024)
k_scan(){
    __shared__ int wsum[32];
    __shared__ int carry;
    int lane = threadIdx.x & 31, w = threadIdx.x >> 5;
    if (threadIdx.x == 0) carry = 0;
    __syncthreads();
    for (int base = 0; base < Nn; base += 1024){
        int i = base + threadIdx.x;
        int v = (i < Nn) ? g_deg[i] : 0;
        int sc = v;
        #pragma unroll
        for (int off=1; off<32; off<<=1){
            int y = __shfl_up_sync(0xffffffffu, sc, off);
            if (lane >= off) sc += y;
        }
        if (lane == 31) wsum[w] = sc;
        __syncthreads();
        if (w == 0){
            int tv = wsum[lane];
            int ts = tv;
            #pragma unroll
            for (int off=1; off<32; off<<=1){
                int y = __shfl_up_sync(0xffffffffu, ts, off);
                if (lane >= off) ts += y;
            }
            wsum[lane] = ts - tv;   // exclusive warp offsets
        }
        __syncthreads();
        int excl = carry + wsum[w] + sc - v;
        if (i < Nn){ g_off[i] = excl; g_cur[i] = excl; }
        __syncthreads();
        if (threadIdx.x == 1023) carry += wsum[31] + sc;
        __syncthreads();
    }
    if (threadIdx.x == 0) g_off[Nn] = Ee;
}

__global__ void __launch_bounds__(256)
k_fill(const int* dst){
    int e = blockIdx.x*blockDim.x + threadIdx.x;
    if (e < Ee){ int p = atomicAdd(&g_cur[dst[e]], 1); g_perm[p] = e; }
}

// ---- per-node P_k = X @ A_k, Q_k = X @ B_k (gated on live intervals) ----
__global__ void __launch_bounds__(256)
k_PQ(const float* xin, int din, int layer){
    int k = blockIdx.y;
    if (g_hist[layer*NK + k] == 0) return;
    const float* A = layer ? g_A1 : g_A0;
    const float* B = layer ? g_B1 : g_B0;
    int D = din*Hh;
    __shared__ float sA[Hh*Hh], sB[Hh*Hh];
    for (int d=threadIdx.x; d<D; d+=blockDim.x){ sA[d]=A[k*D+d]; sB[d]=B[k*D+d]; }
    __syncthreads();
    int lane = threadIdx.x & 31;
    int u = blockIdx.x*(blockDim.x>>5) + (threadIdx.x>>5);
    if (u >= Nn) return;
    float p=0.f, q=0.f;
    const float* xr = xin + (size_t)u*din;
    for (int i=0;i<din;i++){
        float xv = __ldg(xr+i);
        p = fmaf(xv, sA[i*Hh+lane], p);
        q = fmaf(xv, sB[i*Hh+lane], q);
    }
    int o = (k*Nn + u)*Hh + lane;
    g_P[o]=p; g_Q[o]=q;
}

// ---- aggregation: warp per node, lane = output feature; msg = a*P[src] + Q[src] ----
__global__ void __launch_bounds__(256)
k_agg(const float* xin, const float* attr, const int* src,
      const float* root, const float* bias, int din, int layer, float* hout){
    int lane = threadIdx.x & 31;
    int v = blockIdx.x*(blockDim.x>>5) + (threadIdx.x>>5);
    if (v >= Nn) return;
    const unsigned char* ke = layer ? g_k1 : g_k0;
    int s = g_off[v], e1 = g_off[v+1];
    float acc = 0.f;
    for (int base = s; base < e1; base += 32){
        int n = min(32, e1 - base);
        int u=0, kk=0; float a=0.f;
        if (lane < n){ int e = g_perm[base+lane]; u = src[e]; kk = (int)ke[e]; a = attr[e]; }
        for (int t=0; t<n; t++){
            int   ut = __shfl_sync(0xffffffffu, u,  t);
            int   kt = __shfl_sync(0xffffffffu, kk, t);
            float at = __shfl_sync(0xffffffffu, a,  t);
            int o = (kt*Nn + ut)*Hh + lane;
            acc = fmaf(at, g_P[o], acc) + g_Q[o];
        }
    }
    float cnt = (float)(e1 - s);
    acc /= fmaxf(cnt, 1.f);
    float rt = 0.f;
    for (int i=0;i<din;i++) rt = fmaf(__ldg(xin + (size_t)v*din + i), root[i*Hh+lane], rt);
    hout[v*Hh+lane] = rt + acc + bias[lane];
}

// ---- BN stats (sum, sumsq per feature) ----
__global__ void __launch_bounds__(256)
k_stats(const float* h){
    int lane = threadIdx.x & 31;
    int w = threadIdx.x >> 5;
    const int nwarp = 8;
    float s=0.f, s2=0.f;
    for (int v = blockIdx.x*nwarp + w; v < Nn; v += gridDim.x*nwarp){
        float x = h[v*Hh+lane]; s += x; s2 = fmaf(x, x, s2);
    }
    __shared__ float sh[8][Hh], sh2[8][Hh];
    sh[w][lane]=s; sh2[w][lane]=s2;
    __syncthreads();
    if (w == 0){
        float a=0.f, b=0.f;
        for (int i=0;i<nwarp;i++){ a+=sh[i][lane]; b+=sh2[i][lane]; }
        atomicAdd(&g_stats[lane], a); atomicAdd(&g_stats[Hh+lane], b);
    }
}

__global__ void __launch_bounds__(256)
k_apply(const float* h, const float* gamma, const float* beta, float* hn){
    int idx = blockIdx.x*blockDim.x + threadIdx.x;
    if (idx >= Nn*Hh) return;
    int lane = idx & 31;
    float mu  = g_stats[lane]    * (1.f/(float)Nn);
    float var = g_stats[Hh+lane] * (1.f/(float)Nn) - mu*mu;
    float sc  = rsqrtf(var + EPSI) * gamma[lane];
    float x = (h[idx] - mu)*sc + beta[lane];
    hn[idx] = fmaxf(x, 0.f);
}

// ---- global mean pool (batch_ids) ----
__global__ void __launch_bounds__(256)
k_pool(const float* hn, const int* batch){
    int idx = blockIdx.x*blockDim.x + threadIdx.x;
    if (idx >= Nn*Hh) return;
    int v = idx >> 5, lane = idx & 31;
    int g = batch[v];
    atomicAdd(&g_pool[g*Hh+lane], hn[idx]);
    if (lane == 0) atomicAdd(&g_pcnt[g], 1);
}

// ---- readout MLP: [pool, edft] -> 64 -> 1 ----
__global__ void __launch_bounds__(64)
k_mlp(const float* edft, const float* w1, const float* b1,
      const float* w2, const float* b2, float* out){
    int g = threadIdx.x;
    if (g >= Gg) return;
    float zin[Hh+1];
    float inv = 1.f / fmaxf((float)g_pcnt[g], 1.f);
    for (int i=0;i<Hh;i++) zin[i] = g_pool[g*Hh+i]*inv;
    zin[Hh] = edft[g];
    float o = b2[0];
    for (int j=0;j<64;j++){
        float hsum = b1[j];
        #pragma unroll
        for (int i=0;i<Hh+1;i++) hsum = fmaf(zin[i], w1[i*64+j], hsum);
        o = fmaf(fmaxf(hsum, 0.f), w2[j], o);
    }
    out[g] = o;
}

extern "C" void kernel_launch(void* const* d_in, const int* in_sizes, int n_in,
                              void* d_out, int out_size){
    const float* x     = (const float*)d_in[0];
    const float* attr  = (const float*)d_in[1];
    const float* edft  = (const float*)d_in[2];
    const int*   src   = (const int*)  d_in[3];
    const int*   dst   = (const int*)  d_in[4];
    const int*   batch = (const int*)  d_in[5];
    const float* l0w1=(const float*)d_in[6],  *l0b1=(const float*)d_in[7];
    const float* l0w2=(const float*)d_in[8],  *l0b2=(const float*)d_in[9];
    const float* l0root=(const float*)d_in[10],*l0bias=(const float*)d_in[11];
    const float* l0g=(const float*)d_in[12],  *l0be=(const float*)d_in[13];
    const float* l1w1=(const float*)d_in[14], *l1b1=(const float*)d_in[15];
    const float* l1w2=(const float*)d_in[16], *l1b2=(const float*)d_in[17];
    const float* l1root=(const float*)d_in[18],*l1bias=(const float*)d_in[19];
    const float* l1g=(const float*)d_in[20],  *l1be=(const float*)d_in[21];
    const float* mw1=(const float*)d_in[22],  *mb1=(const float*)d_in[23];
    const float* mw2=(const float*)d_in[24],  *mb2=(const float*)d_in[25];
    float* out = (float*)d_out;

    void *pDeg,*pHist,*pStats,*pPool,*pPcnt,*pH,*pHn;
    cudaGetSymbolAddress(&pDeg,   g_deg);
    cudaGetSymbolAddress(&pHist,  g_hist);
    cudaGetSymbolAddress(&pStats, g_stats);
    cudaGetSymbolAddress(&pPool,  g_pool);
    cudaGetSymbolAddress(&pPcnt,  g_pcnt);
    cudaGetSymbolAddress(&pH,     g_h);
    cudaGetSymbolAddress(&pHn,    g_hn);

    cudaMemsetAsync(pDeg,  0, sizeof(int)*Nn);
    cudaMemsetAsync(pHist, 0, sizeof(int)*2*NK);

    k_prep<<<1,64>>>(l0w1,l0b1,l1w1,l1b1);
    k_buildAB<<<NK,256>>>(l0w1,l0b1,l0w2,l0b2,0);
    k_buildAB<<<NK,256>>>(l1w1,l1b1,l1w2,l1b2,1);
    k_edge<<<(Ee+255)/256,256>>>(attr,dst);
    k_scan<<<1,1024>>>();
    k_fill<<<(Ee+255)/256,256>>>(dst);

    // ---- layer 0 ----
    k_PQ<<<dim3((Nn+7)/8, NK),256>>>(x, D0, 0);
    k_agg<<<(Nn+7)/8,256>>>(x, attr, src, l0root, l0bias, D0, 0, (float*)pH);
    cudaMemsetAsync(pStats, 0, sizeof(float)*2*Hh);
    k_stats<<<80,256>>>((const float*)pH);
    k_apply<<<(Nn*Hh+255)/256,256>>>((const float*)pH, l0g, l0be, (float*)pHn);

    // ---- layer 1 ----
    k_PQ<<<dim3((Nn+7)/8, NK),256>>>((const float*)pHn, Hh, 1);
    k_agg<<<(Nn+7)/8,256>>>((const float*)pHn, attr, src, l1root, l1bias, Hh, 1, (float*)pH);
    cudaMemsetAsync(pStats, 0, sizeof(float)*2*Hh);
    k_stats<<<80,256>>>((const float*)pH);
    k_apply<<<(Nn*Hh+255)/256,256>>>((const float*)pH, l1g, l1be, (float*)pHn);

    // ---- pool + readout ----
    cudaMemsetAsync(pPool, 0, sizeof(float)*Gg*Hh);
    cudaMemsetAsync(pPcnt, 0, sizeof(int)*Gg);
    k_pool<<<(Nn*Hh+255)/256,256>>>((const float*)pHn, batch);
    k_mlp<<<1,64>>>(edft, mw1, mb1, mw2, mb2, out);
}

// round 3
// speedup vs baseline: 1.4735x; 1.4735x over previous
#include <cuda_runtime.h>
#include <cfloat>

#define Nn 20000
#define Ee 320000
#define Gg 64
#define D0 16
#define Hh 32
#define NK 33
#define EPSI 1e-5f
#define FULL 0xffffffffu

// ---------------- static device scratch ----------------
__device__ float g_t0[32], g_t1[32];
__device__ int   g_r0[32], g_r1[32];
__device__ float g_A0[NK*D0*Hh], g_B0[NK*D0*Hh];
__device__ float g_A1[NK*Hh*Hh], g_B1[NK*Hh*Hh];
__device__ unsigned char g_k0[Ee], g_k1[Ee];
__device__ int g_hist[2*NK];
__device__ int g_deg[Nn], g_off[Nn+1], g_cur[Nn], g_perm[Ee];
// P and Q interleaved: row of 64 floats per (interval k, node u): [P(32) | Q(32)]
__device__ __align__(16) float g_PQ[(size_t)NK*Nn*64];
__device__ __align__(16) float g_h[Nn*Hh], g_hn[Nn*Hh];
__device__ float g_stats[2*Hh];
__device__ float g_pool[Gg*Hh];
__device__ int   g_pcnt[Gg];

// ---- zero deg/hist + thresholds & stable ranks (block 0, warps 0/1) ----
__global__ void __launch_bounds__(256)
k_prep(const float* w0, const float* b0, const float* w1, const float* b1){
    int gid = blockIdx.x*256 + threadIdx.x;
    for (int i = gid; i < Nn; i += 160*256) g_deg[i] = 0;
    if (gid < 2*NK) g_hist[gid] = 0;
    if (blockIdx.x == 0 && threadIdx.x < 64){
        int warp = threadIdx.x >> 5, j = threadIdx.x & 31;
        const float* W = warp ? w1 : w0;
        const float* B = warp ? b1 : b0;
        float wj = W[j], bj = B[j];
        float t = (wj != 0.0f) ? (-bj / wj) : FLT_MAX;
        int r = 0;
        for (int m = 0; m < 32; m++){
            float tm = __shfl_sync(FULL, t, m);
            if (tm < t || (tm == t && m < j)) r++;
        }
        if (warp){ g_t1[j] = t; g_r1[j] = r; }
        else     { g_t0[j] = t; g_r0[j] = r; }
    }
}

// ---- per-interval collapsed edge-MLP matrices A_k, B_k (both layers, one launch) ----
__global__ void __launch_bounds__(256)
k_buildAB(const float* ew1a, const float* eb1a, const float* ew2a, const float* eb2a,
          const float* ew1b, const float* eb1b, const float* ew2b, const float* eb2b){
    int layer = (blockIdx.x >= NK);
    int k = blockIdx.x - layer*NK;
    int D = layer ? (Hh*Hh) : (D0*Hh);
    float* A = layer ? g_A1 : g_A0;
    float* B = layer ? g_B1 : g_B0;
    const int* rk = layer ? g_r1 : g_r0;
    const float* ew1 = layer ? ew1b : ew1a;
    const float* eb1 = layer ? eb1b : eb1a;
    const float* ew2 = layer ? ew2b : ew2a;
    const float* eb2 = layer ? eb2b : eb2a;
    __shared__ float sw[32], sb[32]; __shared__ int sr[32];
    if (threadIdx.x < 32){
        sw[threadIdx.x]=ew1[threadIdx.x]; sb[threadIdx.x]=eb1[threadIdx.x];
        sr[threadIdx.x]=rk[threadIdx.x];
    }
    __syncthreads();
    for (int d = threadIdx.x; d < D; d += blockDim.x){
        float a = 0.f, b = eb2[d];
        for (int j=0;j<32;j++){
            float wj = sw[j];
            bool act = (wj > 0.f) ? (k > sr[j]) : ((wj < 0.f) ? (k <= sr[j]) : (sb[j] > 0.f));
            if (act){ float w2 = ew2[j*D+d]; a += wj*w2; b += sb[j]*w2; }
        }
        A[k*D+d]=a; B[k*D+d]=b;
    }
}

// ---- per-edge interval index (both layers), warp-aggregated histogram, dst-degree ----
__global__ void __launch_bounds__(256)
k_edge(const float* attr, const int* dst){
    __shared__ float st0[32], st1[32];
    __shared__ int sh[2*NK];
    int t = threadIdx.x, lane = t & 31;
    if (t < 32) st0[t] = g_t0[t];
    else if (t < 64) st1[t-32] = g_t1[t-32];
    if (t < 2*NK) sh[t] = 0;
    __syncthreads();
    int e = blockIdx.x*blockDim.x + t;
    bool valid = (e < Ee);
    float a = valid ? attr[e] : 0.f;
    int k0=0, k1=0;
    #pragma unroll
    for (int j=0;j<32;j++){ k0 += (st0[j] <= a); k1 += (st1[j] <= a); }
    if (valid){
        g_k0[e]=(unsigned char)k0; g_k1[e]=(unsigned char)k1;
        atomicAdd(&g_deg[dst[e]],1);
    }
    // warp-aggregated histogram updates
    int key0 = valid ? k0 : -1;
    unsigned m0 = __match_any_sync(FULL, key0);
    if (valid && lane == (__ffs(m0)-1)) atomicAdd(&sh[k0], __popc(m0));
    int key1 = valid ? k1 : -1;
    unsigned m1 = __match_any_sync(FULL, key1);
    if (valid && lane == (__ffs(m1)-1)) atomicAdd(&sh[NK+k1], __popc(m1));
    __syncthreads();
    if (t < 2*NK && sh[t]) atomicAdd(&g_hist[t], sh[t]);
}

// ---- single-phase exclusive scan: 1024 threads x 20 elements each ----
__global__ void __launch_bounds__(1024)
k_scan(){
    const int PER = 20;
    int t = threadIdx.x, lane = t & 31, w = t >> 5;
    int base = t * PER;
    int loc[PER]; int s = 0;
    #pragma unroll
    for (int j=0;j<PER;j++){ int i=base+j; int v=(i<Nn)?g_deg[i]:0; loc[j]=s; s+=v; }
    int sc = s;
    #pragma unroll
    for (int off=1; off<32; off<<=1){
        int y = __shfl_up_sync(FULL, sc, off);
        if (lane >= off) sc += y;
    }
    __shared__ int wsum[32];
    if (lane == 31) wsum[w] = sc;
    __syncthreads();
    if (w == 0){
        int tv = wsum[lane], ts = tv;
        #pragma unroll
        for (int off=1; off<32; off<<=1){
            int y = __shfl_up_sync(FULL, ts, off);
            if (lane >= off) ts += y;
        }
        wsum[lane] = ts - tv;
    }
    __syncthreads();
    int excl = wsum[w] + sc - s;
    #pragma unroll
    for (int j=0;j<PER;j++){
        int i = base+j;
        if (i < Nn){ int o = excl + loc[j]; g_off[i]=o; g_cur[i]=o; }
    }
    if (t == 0) g_off[Nn] = Ee;
}

__global__ void __launch_bounds__(256)
k_fill(const int* dst){
    int e = blockIdx.x*blockDim.x + threadIdx.x;
    if (e < Ee){ int p = atomicAdd(&g_cur[dst[e]], 1); g_perm[p] = e; }
}

// ---- per-node P_k = X @ A_k, Q_k = X @ B_k : one grid, loop over LIVE intervals ----
__global__ void __launch_bounds__(256)
k_PQ(const float* xin, int din, int layer){
    int lane = threadIdx.x & 31;
    int u = blockIdx.x*8 + (threadIdx.x >> 5);
    if (u >= Nn) return;
    float xv_l = (lane < din) ? __ldg(xin + (size_t)u*din + lane) : 0.f;
    const float* A = layer ? g_A1 : g_A0;
    const float* B = layer ? g_B1 : g_B0;
    int D = din*Hh;
    for (int k = 0; k < NK; k++){
        if (g_hist[layer*NK + k] == 0) continue;
        float p = 0.f, q = 0.f;
        for (int i = 0; i < din; i++){
            float xv = __shfl_sync(FULL, xv_l, i);
            p = fmaf(xv, __ldg(A + k*D + i*Hh + lane), p);
            q = fmaf(xv, __ldg(B + k*D + i*Hh + lane), q);
        }
        size_t ro = ((size_t)(k*Nn + u))*64;
        g_PQ[ro + lane] = p;
        g_PQ[ro + 32 + lane] = q;
    }
}

// ---- aggregation: warp per node; lane = (edge slot 0..3) x (float4 chunk 0..7) ----
// msg_e = a_e * P[k_e, u_e] + Q[k_e, u_e]; 8 edges in flight per iteration.
__global__ void __launch_bounds__(256)
k_agg(const float* xin, const float* attr, const int* src,
      const float* root, const float* bias, int din, int layer, float* hout){
    if (blockIdx.x == 0 && threadIdx.x < 64) g_stats[threadIdx.x] = 0.f;   // fused memset
    int lane = threadIdx.x & 31;
    int v = blockIdx.x*8 + (threadIdx.x >> 5);
    if (v >= Nn) return;
    const unsigned char* ke = layer ? g_k1 : g_k0;
    int s = g_off[v], e1 = g_off[v+1];
    int slot = lane >> 3, c = lane & 7;
    float4 acc0 = {0,0,0,0}, acc1 = {0,0,0,0};
    for (int base = s; base < e1; base += 8){
        int i0 = base + slot, i1 = base + 4 + slot;
        if (i0 < e1){
            int e = g_perm[i0];
            int u = src[e]; float a = attr[e]; int kk = ke[e];
            const float4* row = (const float4*)(g_PQ + ((size_t)(kk*Nn + u))*64);
            float4 p = row[c], q = row[8+c];
            acc0.x = fmaf(a, p.x, acc0.x) + q.x;
            acc0.y = fmaf(a, p.y, acc0.y) + q.y;
            acc0.z = fmaf(a, p.z, acc0.z) + q.z;
            acc0.w = fmaf(a, p.w, acc0.w) + q.w;
        }
        if (i1 < e1){
            int e = g_perm[i1];
            int u = src[e]; float a = attr[e]; int kk = ke[e];
            const float4* row = (const float4*)(g_PQ + ((size_t)(kk*Nn + u))*64);
            float4 p = row[c], q = row[8+c];
            acc1.x = fmaf(a, p.x, acc1.x) + q.x;
            acc1.y = fmaf(a, p.y, acc1.y) + q.y;
            acc1.z = fmaf(a, p.z, acc1.z) + q.z;
            acc1.w = fmaf(a, p.w, acc1.w) + q.w;
        }
    }
    float4 acc;
    acc.x = acc0.x + acc1.x; acc.y = acc0.y + acc1.y;
    acc.z = acc0.z + acc1.z; acc.w = acc0.w + acc1.w;
    #pragma unroll
    for (int off = 8; off < 32; off <<= 1){
        acc.x += __shfl_xor_sync(FULL, acc.x, off);
        acc.y += __shfl_xor_sync(FULL, acc.y, off);
        acc.z += __shfl_xor_sync(FULL, acc.z, off);
        acc.w += __shfl_xor_sync(FULL, acc.w, off);
    }
    if (lane < 8){
        float inv = 1.f / fmaxf((float)(e1 - s), 1.f);
        float4 r = {0,0,0,0};
        for (int i = 0; i < din; i++){
            float xv = __ldg(xin + (size_t)v*din + i);
            const float4 rr = *(const float4*)(root + i*Hh + c*4);
            r.x = fmaf(xv, rr.x, r.x); r.y = fmaf(xv, rr.y, r.y);
            r.z = fmaf(xv, rr.z, r.z); r.w = fmaf(xv, rr.w, r.w);
        }
        float4 b4 = *(const float4*)(bias + c*4);
        float4 o;
        o.x = r.x + acc.x*inv + b4.x;
        o.y = r.y + acc.y*inv + b4.y;
        o.z = r.z + acc.z*inv + b4.z;
        o.w = r.w + acc.w*inv + b4.w;
        ((float4*)hout)[(size_t)v*8 + c] = o;
    }
}

// ---- BN stats (sum, sumsq per feature); layer 1 also zeroes pool buffers ----
__global__ void __launch_bounds__(256)
k_stats(const float* h, int layer){
    if (layer && blockIdx.x == 0){
        for (int i = threadIdx.x; i < Gg*Hh; i += 256) g_pool[i] = 0.f;
        if (threadIdx.x < Gg) g_pcnt[threadIdx.x] = 0;
    }
    int lane = threadIdx.x & 31;
    int w = threadIdx.x >> 5;
    const int nwarp = 8;
    float s = 0.f, s2 = 0.f;
    for (int v = blockIdx.x*nwarp + w; v < Nn; v += gridDim.x*nwarp){
        float x = h[v*Hh + lane]; s += x; s2 = fmaf(x, x, s2);
    }
    __shared__ float sh[8][Hh], sh2[8][Hh];
    sh[w][lane] = s; sh2[w][lane] = s2;
    __syncthreads();
    if (w == 0){
        float a = 0.f, b = 0.f;
        for (int i = 0; i < nwarp; i++){ a += sh[i][lane]; b += sh2[i][lane]; }
        atomicAdd(&g_stats[lane], a); atomicAdd(&g_stats[Hh+lane], b);
    }
}

// ---- BN-apply + ReLU; layer 1 pools directly (no hn write) ----
__global__ void __launch_bounds__(256)
k_apply(const float* h, const float* gamma, const float* beta,
        float* hn, const int* batch, int dopool){
    int idx = blockIdx.x*blockDim.x + threadIdx.x;
    if (idx >= Nn*Hh) return;
    int f = idx & 31, v = idx >> 5;
    float mu  = g_stats[f]    * (1.f/(float)Nn);
    float var = g_stats[Hh+f] * (1.f/(float)Nn) - mu*mu;
    float sc  = rsqrtf(var + EPSI) * gamma[f];
    float xv = fmaxf((h[idx] - mu)*sc + beta[f], 0.f);
    if (dopool){
        int g = batch[v];
        atomicAdd(&g_pool[g*Hh + f], xv);
        if (f == 0) atomicAdd(&g_pcnt[g], 1);
    } else {
        hn[idx] = xv;
    }
}

// ---- readout MLP: [pool, edft] -> 64 -> 1 ----
__global__ void __launch_bounds__(64)
k_mlp(const float* edft, const float* w1, const float* b1,
      const float* w2, const float* b2, float* out){
    int g = threadIdx.x;
    if (g >= Gg) return;
    float zin[Hh+1];
    float inv = 1.f / fmaxf((float)g_pcnt[g], 1.f);
    for (int i = 0; i < Hh; i++) zin[i] = g_pool[g*Hh+i]*inv;
    zin[Hh] = edft[g];
    float o = b2[0];
    for (int j = 0; j < 64; j++){
        float hsum = b1[j];
        #pragma unroll
        for (int i = 0; i < Hh+1; i++) hsum = fmaf(zin[i], w1[i*64+j], hsum);
        o = fmaf(fmaxf(hsum, 0.f), w2[j], o);
    }
    out[g] = o;
}

extern "C" void kernel_launch(void* const* d_in, const int* in_sizes, int n_in,
                              void* d_out, int out_size){
    const float* x     = (const float*)d_in[0];
    const float* attr  = (const float*)d_in[1];
    const float* edft  = (const float*)d_in[2];
    const int*   src   = (const int*)  d_in[3];
    const int*   dst   = (const int*)  d_in[4];
    const int*   batch = (const int*)  d_in[5];
    const float* l0w1=(const float*)d_in[6],  *l0b1=(const float*)d_in[7];
    const float* l0w2=(const float*)d_in[8],  *l0b2=(const float*)d_in[9];
    const float* l0root=(const float*)d_in[10],*l0bias=(const float*)d_in[11];
    const float* l0g=(const float*)d_in[12],  *l0be=(const float*)d_in[13];
    const float* l1w1=(const float*)d_in[14], *l1b1=(const float*)d_in[15];
    const float* l1w2=(const float*)d_in[16], *l1b2=(const float*)d_in[17];
    const float* l1root=(const float*)d_in[18],*l1bias=(const float*)d_in[19];
    const float* l1g=(const float*)d_in[20],  *l1be=(const float*)d_in[21];
    const float* mw1=(const float*)d_in[22],  *mb1=(const float*)d_in[23];
    const float* mw2=(const float*)d_in[24],  *mb2=(const float*)d_in[25];
    float* out = (float*)d_out;

    void *pH, *pHn;
    cudaGetSymbolAddress(&pH,  g_h);
    cudaGetSymbolAddress(&pHn, g_hn);
    float* h  = (float*)pH;
    float* hn = (float*)pHn;

    k_prep<<<160,256>>>(l0w1,l0b1,l1w1,l1b1);
    k_buildAB<<<2*NK,256>>>(l0w1,l0b1,l0w2,l0b2, l1w1,l1b1,l1w2,l1b2);
    k_edge<<<(Ee+255)/256,256>>>(attr,dst);
    k_scan<<<1,1024>>>();
    k_fill<<<(Ee+255)/256,256>>>(dst);

    // ---- layer 0 ----
    k_PQ <<<(Nn+7)/8,256>>>(x, D0, 0);
    k_agg<<<(Nn+7)/8,256>>>(x, attr, src, l0root, l0bias, D0, 0, h);
    k_stats<<<80,256>>>(h, 0);
    k_apply<<<(Nn*Hh+255)/256,256>>>(h, l0g, l0be, hn, batch, 0);

    // ---- layer 1 ----
    k_PQ <<<(Nn+7)/8,256>>>(hn, Hh, 1);
    k_agg<<<(Nn+7)/8,256>>>(hn, attr, src, l1root, l1bias, Hh, 1, h);
    k_stats<<<80,256>>>(h, 1);
    k_apply<<<(Nn*Hh+255)/256,256>>>(h, l1g, l1be, hn, batch, 1);

    // ---- readout ----
    k_mlp<<<1,64>>>(edft, mw1, mb1, mw2, mb2, out);
}

// round 5
// speedup vs baseline: 1.8002x; 1.2217x over previous
#include <cuda_runtime.h>
#include <cfloat>

#define Nn 20000
#define Ee 320000
#define Gg 64
#define D0 16
#define Hh 32
#define NK 33
#define EPSI 1e-5f
#define FULL 0xffffffffu
#define NB_SCAN 20
#define CHUNK 1000

// ---------------- static device scratch (zero-initialized at load; self-cleaning across runs) ----------------
__device__ float g_A0[NK*D0*Hh], g_B0[NK*D0*Hh];
__device__ float g_A1[NK*Hh*Hh], g_B1[NK*Hh*Hh];
__device__ unsigned char g_k0[Ee], g_k1[Ee];
__device__ int g_hist[2*NK];            // zeroed by k_mlp at end of each run
__device__ int g_deg[Nn];               // zeroed by k_scanB after reading
__device__ int g_off[Nn+1], g_cur[Nn];
__device__ int g_bsum[NB_SCAN];
__device__ uint2 g_ebuf[Ee];            // packed per-edge payload in CSR order
__device__ __align__(16) float g_PQ[(size_t)NK*Nn*64];   // [P(32)|Q(32)] per (k,u)
__device__ __align__(16) float g_h[Nn*Hh], g_hn[Nn*Hh];
__device__ float g_stats[2*Hh];         // zeroed by k_PQ block 0 each layer
__device__ float g_pool[Gg*Hh];         // zeroed by k_PQ layer 1 block 0
__device__ int   g_pcnt[Gg];

// ---- helper: thresholds + stable ranks computed in-warp (lane j) ----
__device__ __forceinline__ void rank32(float wj, float bj, float& t, int& r, int j){
    t = (wj != 0.0f) ? (-bj / wj) : FLT_MAX;
    r = 0;
    #pragma unroll
    for (int m = 0; m < 32; m++){
        float tm = __shfl_sync(FULL, t, m);
        r += (tm < t || (tm == t && m < j));
    }
}

// ---- per-interval collapsed edge-MLP matrices A_k, B_k (both layers, one launch) ----
__global__ void __launch_bounds__(256)
k_buildAB(const float* ew1a, const float* eb1a, const float* ew2a, const float* eb2a,
          const float* ew1b, const float* eb1b, const float* ew2b, const float* eb2b){
    int layer = (blockIdx.x >= NK);
    int k = blockIdx.x - layer*NK;
    int D = layer ? (Hh*Hh) : (D0*Hh);
    float* A = layer ? g_A1 : g_A0;
    float* B = layer ? g_B1 : g_B0;
    const float* ew1 = layer ? ew1b : ew1a;
    const float* eb1 = layer ? eb1b : eb1a;
    const float* ew2 = layer ? ew2b : ew2a;
    const float* eb2 = layer ? eb2b : eb2a;
    __shared__ float sw[32], sb[32]; __shared__ int sr[32];
    if (threadIdx.x < 32){
        int j = threadIdx.x;
        float wj = ew1[j], bj = eb1[j], t; int r;
        rank32(wj, bj, t, r, j);
        sw[j]=wj; sb[j]=bj; sr[j]=r;
    }
    __syncthreads();
    for (int d = threadIdx.x; d < D; d += blockDim.x){
        float a = 0.f, b = eb2[d];
        for (int j=0;j<32;j++){
            float wj = sw[j];
            bool act = (wj > 0.f) ? (k > sr[j]) : ((wj < 0.f) ? (k <= sr[j]) : (sb[j] > 0.f));
            if (act){ float w2 = ew2[j*D+d]; a += wj*w2; b += sb[j]*w2; }
        }
        A[k*D+d]=a; B[k*D+d]=b;
    }
}

// ---- per-edge interval via binary search over sorted thresholds; hist + dst-degree ----
__global__ void __launch_bounds__(256)
k_edge(const float* attr, const int* dst,
       const float* ew1a, const float* eb1a, const float* ew1b, const float* eb1b){
    __shared__ float st0[32], st1[32];   // sorted ascending
    __shared__ int sh[2*NK];
    int t = threadIdx.x, lane = t & 31;
    if (t < 32){
        float tv; int r; rank32(ew1a[t], eb1a[t], tv, r, t);
        st0[r] = tv;
    } else if (t < 64){
        int j = t - 32;
        float tv; int r; rank32(ew1b[j], eb1b[j], tv, r, j);
        st1[r] = tv;
    }
    if (t < 2*NK) sh[t] = 0;
    __syncthreads();
    int e = blockIdx.x*blockDim.x + t;
    bool valid = (e < Ee);
    float a = valid ? attr[e] : -FLT_MAX;
    int k0 = 0, k1 = 0;
    #pragma unroll
    for (int step = 16; step > 0; step >>= 1){
        if (st0[k0 + step - 1] <= a) k0 += step;
        if (st1[k1 + step - 1] <= a) k1 += step;
    }
    // 6th comparison: counts range over [0,32], 5 steps only reach 31 (k<=31 here, in-bounds)
    k0 += (st0[k0] <= a);
    k1 += (st1[k1] <= a);
    if (valid){
        g_k0[e]=(unsigned char)k0; g_k1[e]=(unsigned char)k1;
        atomicAdd(&g_deg[dst[e]],1);
    }
    int key0 = valid ? k0 : -1;
    unsigned m0 = __match_any_sync(FULL, key0);
    if (valid && lane == (__ffs(m0)-1)) atomicAdd(&sh[k0], __popc(m0));
    int key1 = valid ? k1 : -1;
    unsigned m1 = __match_any_sync(FULL, key1);
    if (valid && lane == (__ffs(m1)-1)) atomicAdd(&sh[NK+k1], __popc(m1));
    __syncthreads();
    if (t < 2*NK && sh[t]) atomicAdd(&g_hist[t], sh[t]);
}

// ---- scan phase A: per-block degree partial sums ----
__global__ void __launch_bounds__(256)
k_scanA(){
    int b = blockIdx.x, lane = threadIdx.x & 31, w = threadIdx.x >> 5;
    int s = 0;
    for (int i = threadIdx.x; i < CHUNK; i += 256) s += g_deg[b*CHUNK + i];
    #pragma unroll
    for (int off = 16; off; off >>= 1) s += __shfl_xor_sync(FULL, s, off);
    __shared__ int ws[8];
    if (lane == 0) ws[w] = s;
    __syncthreads();
    if (threadIdx.x == 0){
        int tot = 0;
        for (int i = 0; i < 8; i++) tot += ws[i];
        g_bsum[b] = tot;
    }
}

// ---- scan phase B: block-local scan + cross-block base; self-cleans g_deg ----
__global__ void __launch_bounds__(1024)
k_scanB(){
    int b = blockIdx.x, t = threadIdx.x, lane = t & 31, w = t >> 5;
    __shared__ int sbase;
    __shared__ int wsum[32];
    if (t < 32){
        int v = (lane < b) ? g_bsum[lane] : 0;
        #pragma unroll
        for (int off = 16; off; off >>= 1) v += __shfl_xor_sync(FULL, v, off);
        if (lane == 0) sbase = v;
    }
    int i = b*CHUNK + t;
    int v = (t < CHUNK) ? g_deg[i] : 0;
    int sc = v;
    #pragma unroll
    for (int off = 1; off < 32; off <<= 1){
        int y = __shfl_up_sync(FULL, sc, off);
        if (lane >= off) sc += y;
    }
    if (lane == 31) wsum[w] = sc;
    __syncthreads();
    if (w == 0){
        int tv = wsum[lane], ts = tv;
        #pragma unroll
        for (int off = 1; off < 32; off <<= 1){
            int y = __shfl_up_sync(FULL, ts, off);
            if (lane >= off) ts += y;
        }
        wsum[lane] = ts - tv;
    }
    __syncthreads();
    int excl = sbase + wsum[w] + sc - v;
    if (t < CHUNK){ g_off[i] = excl; g_cur[i] = excl; g_deg[i] = 0; }
    if (b == NB_SCAN-1 && t == 0) g_off[Nn] = Ee;
}

// ---- fill CSR slots with packed payload (src | k0<<16 | k1<<24, attr) ----
__global__ void __launch_bounds__(256)
k_fill(const int* dst, const int* src, const float* attr){
    int e = blockIdx.x*blockDim.x + threadIdx.x;
    if (e < Ee){
        unsigned px = (unsigned)src[e] | ((unsigned)g_k0[e] << 16) | ((unsigned)g_k1[e] << 24);
        uint2 pl; pl.x = px; pl.y = __float_as_uint(attr[e]);
        int p = atomicAdd(&g_cur[dst[e]], 1);
        g_ebuf[p] = pl;
    }
}

// ---- per-node P_k = X@A_k, Q_k = X@B_k (live intervals only); zeroes stats/pool ----
__global__ void __launch_bounds__(256)
k_PQ(const float* xin, int din, int layer){
    if (blockIdx.x == 0){
        for (int i = threadIdx.x; i < 2*Hh; i += 256) g_stats[i] = 0.f;
        if (layer){
            for (int i = threadIdx.x; i < Gg*Hh; i += 256) g_pool[i] = 0.f;
            if (threadIdx.x < Gg) g_pcnt[threadIdx.x] = 0;
        }
    }
    int lane = threadIdx.x & 31;
    int u = blockIdx.x*8 + (threadIdx.x >> 5);
    if (u >= Nn) return;
    float xv_l = (lane < din) ? __ldg(xin + (size_t)u*din + lane) : 0.f;
    const float* A = layer ? g_A1 : g_A0;
    const float* B = layer ? g_B1 : g_B0;
    int D = din*Hh;
    for (int k = 0; k < NK; k++){
        if (g_hist[layer*NK + k] == 0) continue;
        float p = 0.f, q = 0.f;
        for (int i = 0; i < din; i++){
            float xv = __shfl_sync(FULL, xv_l, i);
            p = fmaf(xv, __ldg(A + k*D + i*Hh + lane), p);
            q = fmaf(xv, __ldg(B + k*D + i*Hh + lane), q);
        }
        size_t ro = ((size_t)(k*Nn + u))*64;
        g_PQ[ro + lane] = p;
        g_PQ[ro + 32 + lane] = q;
    }
}

// ---- aggregation (warp/node, 8 edges in flight) + fused BN-stat accumulation ----
__global__ void __launch_bounds__(256)
k_agg(const float* xin, const float* root, const float* bias,
      int din, int layer, float* hout){
    __shared__ float ss[Hh], sq[Hh];
    if (threadIdx.x < Hh){ ss[threadIdx.x] = 0.f; sq[threadIdx.x] = 0.f; }
    __syncthreads();
    int lane = threadIdx.x & 31;
    int v = blockIdx.x*8 + (threadIdx.x >> 5);   // grid exact: 2500*8 = Nn
    int shift = 16 + (layer << 3);
    int s = g_off[v], e1 = g_off[v+1];
    int slot = lane >> 3, c = lane & 7;
    float4 acc0 = {0,0,0,0}, acc1 = {0,0,0,0};
    for (int base = s; base < e1; base += 8){
        int i0 = base + slot, i1 = base + 4 + slot;
        if (i0 < e1){
            uint2 pl = g_ebuf[i0];
            int u = pl.x & 0xFFFF; int kk = (pl.x >> shift) & 0xFF;
            float a = __uint_as_float(pl.y);
            const float4* row = (const float4*)(g_PQ + ((size_t)(kk*Nn + u))*64);
            float4 p = row[c], q = row[8+c];
            acc0.x = fmaf(a, p.x, acc0.x) + q.x;
            acc0.y = fmaf(a, p.y, acc0.y) + q.y;
            acc0.z = fmaf(a, p.z, acc0.z) + q.z;
            acc0.w = fmaf(a, p.w, acc0.w) + q.w;
        }
        if (i1 < e1){
            uint2 pl = g_ebuf[i1];
            int u = pl.x & 0xFFFF; int kk = (pl.x >> shift) & 0xFF;
            float a = __uint_as_float(pl.y);
            const float4* row = (const float4*)(g_PQ + ((size_t)(kk*Nn + u))*64);
            float4 p = row[c], q = row[8+c];
            acc1.x = fmaf(a, p.x, acc1.x) + q.x;
            acc1.y = fmaf(a, p.y, acc1.y) + q.y;
            acc1.z = fmaf(a, p.z, acc1.z) + q.z;
            acc1.w = fmaf(a, p.w, acc1.w) + q.w;
        }
    }
    float4 acc;
    acc.x = acc0.x + acc1.x; acc.y = acc0.y + acc1.y;
    acc.z = acc0.z + acc1.z; acc.w = acc0.w + acc1.w;
    #pragma unroll
    for (int off = 8; off < 32; off <<= 1){
        acc.x += __shfl_xor_sync(FULL, acc.x, off);
        acc.y += __shfl_xor_sync(FULL, acc.y, off);
        acc.z += __shfl_xor_sync(FULL, acc.z, off);
        acc.w += __shfl_xor_sync(FULL, acc.w, off);
    }
    if (lane < 8){
        float inv = 1.f / fmaxf((float)(e1 - s), 1.f);
        float4 r = {0,0,0,0};
        for (int i = 0; i < din; i++){
            float xv = __ldg(xin + (size_t)v*din + i);
            const float4 rr = *(const float4*)(root + i*Hh + c*4);
            r.x = fmaf(xv, rr.x, r.x); r.y = fmaf(xv, rr.y, r.y);
            r.z = fmaf(xv, rr.z, r.z); r.w = fmaf(xv, rr.w, r.w);
        }
        float4 b4 = *(const float4*)(bias + c*4);
        float4 o;
        o.x = r.x + acc.x*inv + b4.x;
        o.y = r.y + acc.y*inv + b4.y;
        o.z = r.z + acc.z*inv + b4.z;
        o.w = r.w + acc.w*inv + b4.w;
        ((float4*)hout)[(size_t)v*8 + c] = o;
        int f = c*4;
        atomicAdd(&ss[f+0], o.x); atomicAdd(&sq[f+0], o.x*o.x);
        atomicAdd(&ss[f+1], o.y); atomicAdd(&sq[f+1], o.y*o.y);
        atomicAdd(&ss[f+2], o.z); atomicAdd(&sq[f+2], o.z*o.z);
        atomicAdd(&ss[f+3], o.w); atomicAdd(&sq[f+3], o.w*o.w);
    }
    __syncthreads();
    if (threadIdx.x < Hh){
        atomicAdd(&g_stats[threadIdx.x],      ss[threadIdx.x]);
        atomicAdd(&g_stats[Hh+threadIdx.x],   sq[threadIdx.x]);
    }
}

// ---- BN-apply + ReLU; layer 1 pools directly ----
__global__ void __launch_bounds__(256)
k_apply(const float* h, const float* gamma, const float* beta,
        float* hn, const int* batch, int dopool){
    int idx = blockIdx.x*blockDim.x + threadIdx.x;
    if (idx >= Nn*Hh) return;
    int f = idx & 31, v = idx >> 5;
    float mu  = g_stats[f]    * (1.f/(float)Nn);
    float var = g_stats[Hh+f] * (1.f/(float)Nn) - mu*mu;
    float sc  = rsqrtf(var + EPSI) * gamma[f];
    float xv = fmaxf((h[idx] - mu)*sc + beta[f], 0.f);
    if (dopool){
        int g = batch[v];
        atomicAdd(&g_pool[g*Hh + f], xv);
        if (f == 0) atomicAdd(&g_pcnt[g], 1);
    } else {
        hn[idx] = xv;
    }
}

// ---- readout MLP; self-cleans g_hist ----
__global__ void __launch_bounds__(64)
k_mlp(const float* edft, const float* w1, const float* b1,
      const float* w2, const float* b2, float* out){
    int g = threadIdx.x;
    g_hist[g] = 0;
    if (g < 2*NK - 64) g_hist[64 + g] = 0;
    if (g >= Gg) return;
    float zin[Hh+1];
    float inv = 1.f / fmaxf((float)g_pcnt[g], 1.f);
    for (int i = 0; i < Hh; i++) zin[i] = g_pool[g*Hh+i]*inv;
    zin[Hh] = edft[g];
    float o = b2[0];
    for (int j = 0; j < 64; j++){
        float hsum = b1[j];
        #pragma unroll
        for (int i = 0; i < Hh+1; i++) hsum = fmaf(zin[i], w1[i*64+j], hsum);
        o = fmaf(fmaxf(hsum, 0.f), w2[j], o);
    }
    out[g] = o;
}

extern "C" void kernel_launch(void* const* d_in, const int* in_sizes, int n_in,
                              void* d_out, int out_size){
    const float* x     = (const float*)d_in[0];
    const float* attr  = (const float*)d_in[1];
    const float* edft  = (const float*)d_in[2];
    const int*   src   = (const int*)  d_in[3];
    const int*   dst   = (const int*)  d_in[4];
    const int*   batch = (const int*)  d_in[5];
    const float* l0w1=(const float*)d_in[6],  *l0b1=(const float*)d_in[7];
    const float* l0w2=(const float*)d_in[8],  *l0b2=(const float*)d_in[9];
    const float* l0root=(const float*)d_in[10],*l0bias=(const float*)d_in[11];
    const float* l0g=(const float*)d_in[12],  *l0be=(const float*)d_in[13];
    const float* l1w1=(const float*)d_in[14], *l1b1=(const float*)d_in[15];
    const float* l1w2=(const float*)d_in[16], *l1b2=(const float*)d_in[17];
    const float* l1root=(const float*)d_in[18],*l1bias=(const float*)d_in[19];
    const float* l1g=(const float*)d_in[20],  *l1be=(const float*)d_in[21];
    const float* mw1=(const float*)d_in[22],  *mb1=(const float*)d_in[23];
    const float* mw2=(const float*)d_in[24],  *mb2=(const float*)d_in[25];
    float* out = (float*)d_out;

    void *pH, *pHn;
    cudaGetSymbolAddress(&pH,  g_h);
    cudaGetSymbolAddress(&pHn, g_hn);
    float* h  = (float*)pH;
    float* hn = (float*)pHn;

    k_buildAB<<<2*NK,256>>>(l0w1,l0b1,l0w2,l0b2, l1w1,l1b1,l1w2,l1b2);
    k_edge<<<(Ee+255)/256,256>>>(attr, dst, l0w1,l0b1, l1w1,l1b1);
    k_scanA<<<NB_SCAN,256>>>();
    k_scanB<<<NB_SCAN,1024>>>();
    k_fill<<<(Ee+255)/256,256>>>(dst, src, attr);

    // ---- layer 0 ----
    k_PQ <<<(Nn+7)/8,256>>>(x, D0, 0);
    k_agg<<<Nn/8,256>>>(x, l0root, l0bias, D0, 0, h);
    k_apply<<<(Nn*Hh+255)/256,256>>>(h, l0g, l0be, hn, batch, 0);

    // ---- layer 1 ----
    k_PQ <<<(Nn+7)/8,256>>>(hn, Hh, 1);
    k_agg<<<Nn/8,256>>>(hn, l1root, l1bias, Hh, 1, h);
    k_apply<<<(Nn*Hh+255)/256,256>>>(h, l1g, l1be, hn, batch, 1);

    // ---- readout ----
    k_mlp<<<1,64>>>(edft, mw1, mb1, mw2, mb2, out);
}

// round 6
// speedup vs baseline: 2.4729x; 1.3737x over previous
#include <cuda_runtime.h>
#include <cfloat>

#define Nn 20000
#define Ee 320000
#define Gg 64
#define D0 16
#define Hh 32
#define NK 33
#define EPSI 1e-5f
#define FULL 0xffffffffu
#define NB_SCAN 20
#define CHUNK 1000
#define EDGE_BLKS ((Ee+255)/256)      /* 1250 */
#define AGG_BLKS  (Nn/8)              /* 2500 */

// ---------------- static device scratch (zero-init at load; self-cleaning across replays) ----------------
__device__ float g_A0[NK*D0*Hh], g_B0[NK*D0*Hh];
__device__ float g_A1[NK*Hh*Hh], g_B1[NK*Hh*Hh];
__device__ unsigned char g_k0[Ee], g_k1[Ee];
__device__ int g_hist[2*NK];            // zeroed by k_mlp each run
__device__ int g_deg[Nn];               // zeroed by k_scanB after read
__device__ int g_off[Nn+1], g_cur[Nn];
__device__ int g_bsum[NB_SCAN];
__device__ int g_nlive[2], g_klive[2];
__device__ uint2 g_ebuf[Ee];            // CSR-ordered packed payload (src|k0<<16|k1<<24, attr)
__device__ __align__(16) float g_PQ[(size_t)NK*Nn*64];   // general path only
__device__ __align__(16) float g_h[Nn*Hh], g_hn[Nn*Hh];
__device__ float g_stats[4*Hh];         // [sum0|sq0|sum1|sq1], zeroed by k_pre block 0
__device__ float g_pool[Gg*Hh];
__device__ int   g_pcnt[Gg];

__device__ __forceinline__ void rank32(float wj, float bj, float& t, int& r, int j){
    t = (wj != 0.0f) ? (-bj / wj) : FLT_MAX;
    r = 0;
    #pragma unroll
    for (int m = 0; m < 32; m++){
        float tm = __shfl_sync(FULL, t, m);
        r += (tm < t || (tm == t && m < j));
    }
}

// ==== fused: blocks [0,2*NK) buildAB, blocks [2*NK, ...) per-edge interval/hist/deg ====
__global__ void __launch_bounds__(256)
k_pre(const float* attr, const int* dst,
      const float* ew1a, const float* eb1a, const float* ew2a, const float* eb2a,
      const float* ew1b, const float* eb1b, const float* ew2b, const float* eb2b){
    int t = threadIdx.x;
    if (blockIdx.x < 2*NK){
        if (blockIdx.x == 0){   // zero stats/pool/pcnt for this run
            for (int i = t; i < 4*Hh; i += 256) g_stats[i] = 0.f;
            for (int i = t; i < Gg*Hh; i += 256) g_pool[i] = 0.f;
            if (t < Gg) g_pcnt[t] = 0;
        }
        int layer = (blockIdx.x >= NK);
        int k = blockIdx.x - layer*NK;
        int D = layer ? (Hh*Hh) : (D0*Hh);
        float* A = layer ? g_A1 : g_A0;
        float* B = layer ? g_B1 : g_B0;
        const float* ew1 = layer ? ew1b : ew1a;
        const float* eb1 = layer ? eb1b : eb1a;
        const float* ew2 = layer ? ew2b : ew2a;
        const float* eb2 = layer ? eb2b : eb2a;
        __shared__ float sw[32], sb[32]; __shared__ int sr[32];
        if (t < 32){
            float wj = ew1[t], bj = eb1[t], tv; int r;
            rank32(wj, bj, tv, r, t);
            sw[t]=wj; sb[t]=bj; sr[t]=r;
        }
        __syncthreads();
        for (int d = t; d < D; d += 256){
            float a = 0.f, b = eb2[d];
            for (int j=0;j<32;j++){
                float wj = sw[j];
                bool act = (wj > 0.f) ? (k > sr[j]) : ((wj < 0.f) ? (k <= sr[j]) : (sb[j] > 0.f));
                if (act){ float w2 = ew2[j*D+d]; a += wj*w2; b += sb[j]*w2; }
            }
            A[k*D+d]=a; B[k*D+d]=b;
        }
        return;
    }
    // ---- edge role ----
    __shared__ float st0[32], st1[32];
    __shared__ int sh[2*NK];
    int lane = t & 31;
    if (t < 32){ float tv; int r; rank32(ew1a[t], eb1a[t], tv, r, t); st0[r]=tv; }
    else if (t < 64){ int j=t-32; float tv; int r; rank32(ew1b[j], eb1b[j], tv, r, j); st1[r]=tv; }
    if (t < 2*NK) sh[t] = 0;
    __syncthreads();
    int e = (blockIdx.x - 2*NK)*256 + t;
    bool valid = (e < Ee);
    float a = valid ? attr[e] : -FLT_MAX;
    int k0 = 0, k1 = 0;
    #pragma unroll
    for (int step = 16; step > 0; step >>= 1){
        if (st0[k0 + step - 1] <= a) k0 += step;
        if (st1[k1 + step - 1] <= a) k1 += step;
    }
    k0 += (st0[k0] <= a);   // counts range [0,32]
    k1 += (st1[k1] <= a);
    if (valid){
        g_k0[e]=(unsigned char)k0; g_k1[e]=(unsigned char)k1;
        atomicAdd(&g_deg[dst[e]],1);
    }
    int key0 = valid ? k0 : -1;
    unsigned m0 = __match_any_sync(FULL, key0);
    if (valid && lane == (__ffs(m0)-1)) atomicAdd(&sh[k0], __popc(m0));
    int key1 = valid ? k1 : -1;
    unsigned m1 = __match_any_sync(FULL, key1);
    if (valid && lane == (__ffs(m1)-1)) atomicAdd(&sh[NK+k1], __popc(m1));
    __syncthreads();
    if (t < 2*NK && sh[t]) atomicAdd(&g_hist[t], sh[t]);
}

// ==== scan phase A + live-interval detection ====
__global__ void __launch_bounds__(256)
k_scanA(){
    int b = blockIdx.x, lane = threadIdx.x & 31, w = threadIdx.x >> 5;
    if (b == 0 && threadIdx.x < 2){
        int base = threadIdx.x*NK, n = 0, kl = 0;
        for (int k = 0; k < NK; k++) if (g_hist[base+k] > 0){ n++; kl = k; }
        g_nlive[threadIdx.x] = n; g_klive[threadIdx.x] = kl;
    }
    int s = 0;
    for (int i = threadIdx.x; i < CHUNK; i += 256) s += g_deg[b*CHUNK + i];
    #pragma unroll
    for (int off = 16; off; off >>= 1) s += __shfl_xor_sync(FULL, s, off);
    __shared__ int ws[8];
    if (lane == 0) ws[w] = s;
    __syncthreads();
    if (threadIdx.x == 0){
        int tot = 0;
        for (int i = 0; i < 8; i++) tot += ws[i];
        g_bsum[b] = tot;
    }
}

// ==== scan phase B: exclusive offsets; self-cleans g_deg ====
__global__ void __launch_bounds__(1024)
k_scanB(){
    int b = blockIdx.x, t = threadIdx.x, lane = t & 31, w = t >> 5;
    __shared__ int sbase;
    __shared__ int wsum[32];
    if (t < 32){
        int v = (lane < b) ? g_bsum[lane] : 0;
        #pragma unroll
        for (int off = 16; off; off >>= 1) v += __shfl_xor_sync(FULL, v, off);
        if (lane == 0) sbase = v;
    }
    int i = b*CHUNK + t;
    int v = (t < CHUNK) ? g_deg[i] : 0;
    int sc = v;
    #pragma unroll
    for (int off = 1; off < 32; off <<= 1){
        int y = __shfl_up_sync(FULL, sc, off);
        if (lane >= off) sc += y;
    }
    if (lane == 31) wsum[w] = sc;
    __syncthreads();
    if (w == 0){
        int tv = wsum[lane], ts = tv;
        #pragma unroll
        for (int off = 1; off < 32; off <<= 1){
            int y = __shfl_up_sync(FULL, ts, off);
            if (lane >= off) ts += y;
        }
        wsum[lane] = ts - tv;
    }
    __syncthreads();
    int excl = sbase + wsum[w] + sc - v;
    if (t < CHUNK){ g_off[i] = excl; g_cur[i] = excl; g_deg[i] = 0; }
    if (b == NB_SCAN-1 && t == 0) g_off[Nn] = Ee;
}

// ==== fused: blocks [0,EDGE_BLKS) CSR fill; blocks [EDGE_BLKS,..) PQ layer 0 (general path only) ====
__global__ void __launch_bounds__(256)
k_fillPQ(const int* dst, const int* src, const float* attr, const float* xin){
    if (blockIdx.x < EDGE_BLKS){
        int e = blockIdx.x*256 + threadIdx.x;
        if (e < Ee){
            unsigned px = (unsigned)src[e] | ((unsigned)g_k0[e] << 16) | ((unsigned)g_k1[e] << 24);
            uint2 pl; pl.x = px; pl.y = __float_as_uint(attr[e]);
            int p = atomicAdd(&g_cur[dst[e]], 1);
            g_ebuf[p] = pl;
        }
        return;
    }
    if (g_nlive[0] == 1) return;     // fast path: PQ not needed
    int lane = threadIdx.x & 31;
    int u = (blockIdx.x - EDGE_BLKS)*8 + (threadIdx.x >> 5);
    if (u >= Nn) return;
    float xv_l = (lane < D0) ? __ldg(xin + (size_t)u*D0 + lane) : 0.f;
    for (int k = 0; k < NK; k++){
        if (g_hist[k] == 0) continue;
        float p = 0.f, q = 0.f;
        for (int i = 0; i < D0; i++){
            float xv = __shfl_sync(FULL, xv_l, i);
            p = fmaf(xv, __ldg(g_A0 + k*D0*Hh + i*Hh + lane), p);
            q = fmaf(xv, __ldg(g_B0 + k*D0*Hh + i*Hh + lane), q);
        }
        size_t ro = ((size_t)(k*Nn + u))*64;
        g_PQ[ro + lane] = p;
        g_PQ[ro + 32 + lane] = q;
    }
}

// ==== PQ layer 1 (general path only; BN+ReLU inline from layer-0 stats) ====
__global__ void __launch_bounds__(256)
k_PQ1(const float* gamma, const float* beta){
    if (g_nlive[1] == 1) return;
    int lane = threadIdx.x & 31;
    int u = blockIdx.x*8 + (threadIdx.x >> 5);
    if (u >= Nn) return;
    float mu  = g_stats[lane]    * (1.f/(float)Nn);
    float var = g_stats[32+lane] * (1.f/(float)Nn) - mu*mu;
    float sc  = rsqrtf(var + EPSI) * __ldg(gamma+lane);
    float shf = __ldg(beta+lane) - mu*sc;
    float xv_l = fmaxf(g_h[(size_t)u*32 + lane]*sc + shf, 0.f);
    for (int k = 0; k < NK; k++){
        if (g_hist[NK + k] == 0) continue;
        float p = 0.f, q = 0.f;
        for (int i = 0; i < Hh; i++){
            float xv = __shfl_sync(FULL, xv_l, i);
            p = fmaf(xv, __ldg(g_A1 + k*Hh*Hh + i*Hh + lane), p);
            q = fmaf(xv, __ldg(g_B1 + k*Hh*Hh + i*Hh + lane), q);
        }
        size_t ro = ((size_t)(k*Nn + u))*64;
        g_PQ[ro + lane] = p;
        g_PQ[ro + 32 + lane] = q;
    }
}

// ==== aggregation: warp/node. Fast path (nlive==1): gather raw x rows, factorized A/B.
//      General path: gather P/Q rows. BN+ReLU inline on inputs for LAYER==1. ====
template<int DIN, int LAYER>
__global__ void __launch_bounds__(256)
k_agg(const float* __restrict__ xin, const float* __restrict__ root,
      const float* __restrict__ bias, const float* __restrict__ gamma0,
      const float* __restrict__ beta0, float* __restrict__ hout){
    constexpr int NC = DIN/4;        // float4 chunks per x row
    constexpr int NS = 32/NC;        // edge slots per warp iteration (fast path)
    __shared__ float sA[DIN*32], sB[DIN*32], sR[DIN*32];
    __shared__ float sScale[32], sShift[32];
    __shared__ float sAcc[8][2*DIN];
    __shared__ float ss[32], sq[32];
    int t = threadIdx.x, lane = t & 31, w = t >> 5;
    int nlive = g_nlive[LAYER];
    int kl = g_klive[LAYER];
    if (t < 32){ ss[t] = 0.f; sq[t] = 0.f; }
    if (LAYER == 1 && t < 32){
        float mu  = g_stats[t]    * (1.f/(float)Nn);
        float var = g_stats[32+t] * (1.f/(float)Nn) - mu*mu;
        float sc  = rsqrtf(var + EPSI) * __ldg(gamma0+t);
        sScale[t] = sc;
        sShift[t] = __ldg(beta0+t) - mu*sc;
    }
    for (int d = t; d < DIN*32; d += 256) sR[d] = __ldg(root + d);
    if (nlive == 1){
        const float* A = LAYER ? g_A1 : g_A0;
        const float* B = LAYER ? g_B1 : g_B0;
        for (int d = t; d < DIN*32; d += 256){
            sA[d] = __ldg(A + kl*DIN*32 + d);
            sB[d] = __ldg(B + kl*DIN*32 + d);
        }
    }
    __syncthreads();

    int v = blockIdx.x*8 + w;                 // grid exact: 2500*8 = Nn
    int s = g_off[v], e1 = g_off[v+1];
    float msg;
    if (nlive == 1){
        // ---------- fast path ----------
        int slot = lane / NC, c = lane % NC;
        float4 ya = {0,0,0,0}, yb = {0,0,0,0};
        for (int base = s; base < e1; base += NS){
            int i = base + slot;
            if (i < e1){
                uint2 pl = g_ebuf[i];
                int u = pl.x & 0xFFFF;
                float a = __uint_as_float(pl.y);
                float4 xc = ((const float4*)xin)[(size_t)u*NC + c];
                if (LAYER == 1){
                    int f = c*4;
                    xc.x = fmaxf(xc.x*sScale[f+0] + sShift[f+0], 0.f);
                    xc.y = fmaxf(xc.y*sScale[f+1] + sShift[f+1], 0.f);
                    xc.z = fmaxf(xc.z*sScale[f+2] + sShift[f+2], 0.f);
                    xc.w = fmaxf(xc.w*sScale[f+3] + sShift[f+3], 0.f);
                }
                ya.x = fmaf(a, xc.x, ya.x); yb.x += xc.x;
                ya.y = fmaf(a, xc.y, ya.y); yb.y += xc.y;
                ya.z = fmaf(a, xc.z, ya.z); yb.z += xc.z;
                ya.w = fmaf(a, xc.w, ya.w); yb.w += xc.w;
            }
        }
        #pragma unroll
        for (int off = NC; off < 32; off <<= 1){
            ya.x += __shfl_xor_sync(FULL, ya.x, off);
            ya.y += __shfl_xor_sync(FULL, ya.y, off);
            ya.z += __shfl_xor_sync(FULL, ya.z, off);
            ya.w += __shfl_xor_sync(FULL, ya.w, off);
            yb.x += __shfl_xor_sync(FULL, yb.x, off);
            yb.y += __shfl_xor_sync(FULL, yb.y, off);
            yb.z += __shfl_xor_sync(FULL, yb.z, off);
            yb.w += __shfl_xor_sync(FULL, yb.w, off);
        }
        if (lane < NC){
            int f = lane*4;
            sAcc[w][f+0] = ya.x; sAcc[w][f+1] = ya.y;
            sAcc[w][f+2] = ya.z; sAcc[w][f+3] = ya.w;
            sAcc[w][DIN+f+0] = yb.x; sAcc[w][DIN+f+1] = yb.y;
            sAcc[w][DIN+f+2] = yb.z; sAcc[w][DIN+f+3] = yb.w;
        }
        __syncwarp();
        msg = 0.f;
        #pragma unroll
        for (int i = 0; i < DIN; i++){
            msg = fmaf(sAcc[w][i],     sA[i*32+lane], msg);
            msg = fmaf(sAcc[w][DIN+i], sB[i*32+lane], msg);
        }
    } else {
        // ---------- general path: gather P/Q rows ----------
        int shift = 16 + (LAYER << 3);
        int slot = lane >> 3, c = lane & 7;
        float4 acc = {0,0,0,0};
        for (int base = s; base < e1; base += 4){
            int i = base + slot;
            if (i < e1){
                uint2 pl = g_ebuf[i];
                int u = pl.x & 0xFFFF; int kk = (pl.x >> shift) & 0xFF;
                float a = __uint_as_float(pl.y);
                const float4* row = (const float4*)(g_PQ + ((size_t)(kk*Nn + u))*64);
                float4 p = row[c], q = row[8+c];
                acc.x = fmaf(a, p.x, acc.x) + q.x;
                acc.y = fmaf(a, p.y, acc.y) + q.y;
                acc.z = fmaf(a, p.z, acc.z) + q.z;
                acc.w = fmaf(a, p.w, acc.w) + q.w;
            }
        }
        #pragma unroll
        for (int off = 8; off < 32; off <<= 1){
            acc.x += __shfl_xor_sync(FULL, acc.x, off);
            acc.y += __shfl_xor_sync(FULL, acc.y, off);
            acc.z += __shfl_xor_sync(FULL, acc.z, off);
            acc.w += __shfl_xor_sync(FULL, acc.w, off);
        }
        if (lane < 8){
            int f = lane*4;
            sAcc[w][f+0] = acc.x; sAcc[w][f+1] = acc.y;
            sAcc[w][f+2] = acc.z; sAcc[w][f+3] = acc.w;
        }
        __syncwarp();
        msg = sAcc[w][lane];
    }

    // ---------- common epilogue ----------
    float inv = 1.f / fmaxf((float)(e1 - s), 1.f);
    float xv = 0.f;
    if (lane < DIN){
        xv = __ldg(xin + (size_t)v*DIN + lane);
        if (LAYER == 1) xv = fmaxf(xv*sScale[lane] + sShift[lane], 0.f);
    }
    float rt = 0.f;
    #pragma unroll
    for (int i = 0; i < DIN; i++)
        rt = fmaf(__shfl_sync(FULL, xv, i), sR[i*32+lane], rt);
    float o = rt + msg*inv + __ldg(bias+lane);
    hout[(size_t)v*32 + lane] = o;
    atomicAdd(&ss[lane], o);
    atomicAdd(&sq[lane], o*o);
    __syncthreads();
    if (t < 32){
        atomicAdd(&g_stats[LAYER*64 + t],      ss[t]);
        atomicAdd(&g_stats[LAYER*64 + 32 + t], sq[t]);
    }
}

// ==== BN2 + ReLU + pooling (layer-1 stats) ====
__global__ void __launch_bounds__(256)
k_apply1(const float* h2, const float* gamma, const float* beta, const int* batch){
    int idx = blockIdx.x*blockDim.x + threadIdx.x;
    if (idx >= Nn*Hh) return;
    int f = idx & 31, v = idx >> 5;
    float mu  = g_stats[64+f] * (1.f/(float)Nn);
    float var = g_stats[96+f] * (1.f/(float)Nn) - mu*mu;
    float sc  = rsqrtf(var + EPSI) * __ldg(gamma+f);
    float xv = fmaxf((h2[idx] - mu)*sc + __ldg(beta+f), 0.f);
    int g = batch[v];
    atomicAdd(&g_pool[g*Hh + f], xv);
    if (f == 0) atomicAdd(&g_pcnt[g], 1);
}

// ==== readout MLP; self-cleans g_hist ====
__global__ void __launch_bounds__(64)
k_mlp(const float* edft, const float* w1, const float* b1,
      const float* w2, const float* b2, float* out){
    int g = threadIdx.x;
    g_hist[g] = 0;
    if (g < 2*NK - 64) g_hist[64 + g] = 0;
    if (g >= Gg) return;
    float zin[Hh+1];
    float inv = 1.f / fmaxf((float)g_pcnt[g], 1.f);
    for (int i = 0; i < Hh; i++) zin[i] = g_pool[g*Hh+i]*inv;
    zin[Hh] = edft[g];
    float o = b2[0];
    for (int j = 0; j < 64; j++){
        float hsum = b1[j];
        #pragma unroll
        for (int i = 0; i < Hh+1; i++) hsum = fmaf(zin[i], w1[i*64+j], hsum);
        o = fmaf(fmaxf(hsum, 0.f), w2[j], o);
    }
    out[g] = o;
}

extern "C" void kernel_launch(void* const* d_in, const int* in_sizes, int n_in,
                              void* d_out, int out_size){
    const float* x     = (const float*)d_in[0];
    const float* attr  = (const float*)d_in[1];
    const float* edft  = (const float*)d_in[2];
    const int*   src   = (const int*)  d_in[3];
    const int*   dst   = (const int*)  d_in[4];
    const int*   batch = (const int*)  d_in[5];
    const float* l0w1=(const float*)d_in[6],  *l0b1=(const float*)d_in[7];
    const float* l0w2=(const float*)d_in[8],  *l0b2=(const float*)d_in[9];
    const float* l0root=(const float*)d_in[10],*l0bias=(const float*)d_in[11];
    const float* l0g=(const float*)d_in[12],  *l0be=(const float*)d_in[13];
    const float* l1w1=(const float*)d_in[14], *l1b1=(const float*)d_in[15];
    const float* l1w2=(const float*)d_in[16], *l1b2=(const float*)d_in[17];
    const float* l1root=(const float*)d_in[18],*l1bias=(const float*)d_in[19];
    const float* l1g=(const float*)d_in[20],  *l1be=(const float*)d_in[21];
    const float* mw1=(const float*)d_in[22],  *mb1=(const float*)d_in[23];
    const float* mw2=(const float*)d_in[24],  *mb2=(const float*)d_in[25];
    float* out = (float*)d_out;

    void *pH, *pHn;
    cudaGetSymbolAddress(&pH,  g_h);
    cudaGetSymbolAddress(&pHn, g_hn);
    float* h  = (float*)pH;
    float* h2 = (float*)pHn;

    k_pre<<<2*NK + EDGE_BLKS, 256>>>(attr, dst,
                                     l0w1,l0b1,l0w2,l0b2, l1w1,l1b1,l1w2,l1b2);
    k_scanA<<<NB_SCAN,256>>>();
    k_scanB<<<NB_SCAN,1024>>>();
    k_fillPQ<<<EDGE_BLKS + AGG_BLKS, 256>>>(dst, src, attr, x);

    k_agg<D0,0><<<AGG_BLKS,256>>>(x, l0root, l0bias, l0g, l0be, h);
    k_PQ1<<<AGG_BLKS,256>>>(l0g, l0be);
    k_agg<Hh,1><<<AGG_BLKS,256>>>(h, l1root, l1bias, l0g, l0be, h2);
    k_apply1<<<(Nn*Hh+255)/256,256>>>(h2, l1g, l1be, batch);
    k_mlp<<<1,64>>>(edft, mw1, mb1, mw2, mb2, out);
}

// round 7
// speedup vs baseline: 2.5306x; 1.0233x over previous
#include <cuda_runtime.h>
#include <cfloat>

#define Nn 20000
#define Ee 320000
#define Gg 64
#define D0 16
#define Hh 32
#define NK 33
#define EPSI 1e-5f
#define FULL 0xffffffffu
#define EDGE_BLKS ((Ee+255)/256)      /* 1250 */
#define AGG_BLKS  (Nn/8)              /* 2500 */

// ---------------- static device scratch (zero-init at load; self-cleaning across replays) ----------------
__device__ float g_A0[NK*D0*Hh], g_B0[NK*D0*Hh];
__device__ float g_A1[NK*Hh*Hh], g_B1[NK*Hh*Hh];
__device__ unsigned char g_k0[Ee], g_k1[Ee];
__device__ int g_hist[2*NK];            // zeroed by k_mlp each run
__device__ int g_deg[Nn];               // zeroed by k_alloc after read
__device__ int g_total;                 // zeroed by k_mlp each run
__device__ int g_off[Nn], g_end[Nn], g_cur[Nn];
__device__ int g_nlive[2], g_klive[2];
__device__ uint2 g_ebuf[Ee];            // CSR-ordered packed payload
__device__ __align__(16) float g_PQ[(size_t)NK*Nn*64];   // general path only
__device__ __align__(16) float g_h[Nn*Hh], g_hn[Nn*Hh];
__device__ float g_stats[4*Hh];         // [sum0|sq0|sum1|sq1], zeroed by k_pre block 0
__device__ float g_pool[Gg*Hh];
__device__ int   g_pcnt[Gg];

__device__ __forceinline__ void rank32(float wj, float bj, float& t, int& r, int j){
    t = (wj != 0.0f) ? (-bj / wj) : FLT_MAX;
    r = 0;
    #pragma unroll
    for (int m = 0; m < 32; m++){
        float tm = __shfl_sync(FULL, t, m);
        r += (tm < t || (tm == t && m < j));
    }
}

// ==== fused: blocks [0,2*NK) buildAB, blocks [2*NK,...) per-edge interval/hist/deg ====
__global__ void __launch_bounds__(256)
k_pre(const float* attr, const int* dst,
      const float* ew1a, const float* eb1a, const float* ew2a, const float* eb2a,
      const float* ew1b, const float* eb1b, const float* ew2b, const float* eb2b){
    int t = threadIdx.x;
    if (blockIdx.x < 2*NK){
        if (blockIdx.x == 0){
            for (int i = t; i < 4*Hh; i += 256) g_stats[i] = 0.f;
            for (int i = t; i < Gg*Hh; i += 256) g_pool[i] = 0.f;
            if (t < Gg) g_pcnt[t] = 0;
        }
        int layer = (blockIdx.x >= NK);
        int k = blockIdx.x - layer*NK;
        int D = layer ? (Hh*Hh) : (D0*Hh);
        float* A = layer ? g_A1 : g_A0;
        float* B = layer ? g_B1 : g_B0;
        const float* ew1 = layer ? ew1b : ew1a;
        const float* eb1 = layer ? eb1b : eb1a;
        const float* ew2 = layer ? ew2b : ew2a;
        const float* eb2 = layer ? eb2b : eb2a;
        __shared__ float sw[32], sb[32]; __shared__ int sr[32];
        if (t < 32){
            float wj = ew1[t], bj = eb1[t], tv; int r;
            rank32(wj, bj, tv, r, t);
            sw[t]=wj; sb[t]=bj; sr[t]=r;
        }
        __syncthreads();
        for (int d = t; d < D; d += 256){
            float a = 0.f, b = eb2[d];
            for (int j=0;j<32;j++){
                float wj = sw[j];
                bool act = (wj > 0.f) ? (k > sr[j]) : ((wj < 0.f) ? (k <= sr[j]) : (sb[j] > 0.f));
                if (act){ float w2 = ew2[j*D+d]; a += wj*w2; b += sb[j]*w2; }
            }
            A[k*D+d]=a; B[k*D+d]=b;
        }
        return;
    }
    // ---- edge role ----
    __shared__ float st0[32], st1[32];
    __shared__ int sh[2*NK];
    int lane = t & 31;
    if (t < 32){ float tv; int r; rank32(ew1a[t], eb1a[t], tv, r, t); st0[r]=tv; }
    else if (t < 64){ int j=t-32; float tv; int r; rank32(ew1b[j], eb1b[j], tv, r, j); st1[r]=tv; }
    if (t < 2*NK) sh[t] = 0;
    __syncthreads();
    int e = (blockIdx.x - 2*NK)*256 + t;
    bool valid = (e < Ee);
    float a = valid ? attr[e] : -FLT_MAX;
    int k0 = 0, k1 = 0;
    #pragma unroll
    for (int step = 16; step > 0; step >>= 1){
        if (st0[k0 + step - 1] <= a) k0 += step;
        if (st1[k1 + step - 1] <= a) k1 += step;
    }
    k0 += (st0[k0] <= a);   // counts range [0,32]
    k1 += (st1[k1] <= a);
    if (valid){
        g_k0[e]=(unsigned char)k0; g_k1[e]=(unsigned char)k1;
        atomicAdd(&g_deg[dst[e]],1);
    }
    int key0 = valid ? k0 : -1;
    unsigned m0 = __match_any_sync(FULL, key0);
    if (valid && lane == (__ffs(m0)-1)) atomicAdd(&sh[k0], __popc(m0));
    int key1 = valid ? k1 : -1;
    unsigned m1 = __match_any_sync(FULL, key1);
    if (valid && lane == (__ffs(m1)-1)) atomicAdd(&sh[NK+k1], __popc(m1));
    __syncthreads();
    if (t < 2*NK && sh[t]) atomicAdd(&g_hist[t], sh[t]);
}

// ==== segment allocation: warp-aggregated atomic bump; order-free CSR. Also nlive detect. ====
__global__ void __launch_bounds__(256)
k_alloc(){
    int i = blockIdx.x*256 + threadIdx.x;
    int lane = threadIdx.x & 31;
    if (blockIdx.x == 0 && threadIdx.x < 2){
        int base = threadIdx.x*NK, n = 0, kl = 0;
        for (int k = 0; k < NK; k++) if (g_hist[base+k] > 0){ n++; kl = k; }
        g_nlive[threadIdx.x] = n; g_klive[threadIdx.x] = kl;
    }
    int d = (i < Nn) ? g_deg[i] : 0;
    int sc = d;
    #pragma unroll
    for (int off = 1; off < 32; off <<= 1){
        int y = __shfl_up_sync(FULL, sc, off);
        if (lane >= off) sc += y;
    }
    int tot = __shfl_sync(FULL, sc, 31);
    int base = 0;
    if (lane == 31 && tot) base = atomicAdd(&g_total, tot);
    base = __shfl_sync(FULL, base, 31);
    if (i < Nn){
        int my = base + sc - d;
        g_off[i] = my; g_cur[i] = my; g_end[i] = my + d;
        g_deg[i] = 0;
    }
}

// ==== fused: blocks [0,EDGE_BLKS) CSR fill; blocks [EDGE_BLKS,..) PQ layer 0 (general only) ====
__global__ void __launch_bounds__(256)
k_fillPQ(const int* dst, const int* src, const float* attr, const float* xin){
    if (blockIdx.x < EDGE_BLKS){
        bool fastboth = (g_nlive[0] == 1) & (g_nlive[1] == 1);
        int e = blockIdx.x*256 + threadIdx.x;
        if (e < Ee){
            unsigned px = (unsigned)src[e];
            if (!fastboth)
                px |= ((unsigned)g_k0[e] << 16) | ((unsigned)g_k1[e] << 24);
            uint2 pl; pl.x = px; pl.y = __float_as_uint(attr[e]);
            int p = atomicAdd(&g_cur[dst[e]], 1);
            g_ebuf[p] = pl;
        }
        return;
    }
    if (g_nlive[0] == 1) return;     // fast path: PQ not needed
    int lane = threadIdx.x & 31;
    int u = (blockIdx.x - EDGE_BLKS)*8 + (threadIdx.x >> 5);
    if (u >= Nn) return;
    float xv_l = (lane < D0) ? __ldg(xin + (size_t)u*D0 + lane) : 0.f;
    for (int k = 0; k < NK; k++){
        if (g_hist[k] == 0) continue;
        float p = 0.f, q = 0.f;
        for (int i = 0; i < D0; i++){
            float xv = __shfl_sync(FULL, xv_l, i);
            p = fmaf(xv, __ldg(g_A0 + k*D0*Hh + i*Hh + lane), p);
            q = fmaf(xv, __ldg(g_B0 + k*D0*Hh + i*Hh + lane), q);
        }
        size_t ro = ((size_t)(k*Nn + u))*64;
        g_PQ[ro + lane] = p;
        g_PQ[ro + 32 + lane] = q;
    }
}

// ==== PQ layer 1 (general path only; BN+ReLU inline from layer-0 stats) ====
__global__ void __launch_bounds__(256)
k_PQ1(const float* gamma, const float* beta){
    if (g_nlive[1] == 1) return;
    int lane = threadIdx.x & 31;
    int u = blockIdx.x*8 + (threadIdx.x >> 5);
    if (u >= Nn) return;
    float mu  = g_stats[lane]    * (1.f/(float)Nn);
    float var = g_stats[32+lane] * (1.f/(float)Nn) - mu*mu;
    float sc  = rsqrtf(var + EPSI) * __ldg(gamma+lane);
    float shf = __ldg(beta+lane) - mu*sc;
    float xv_l = fmaxf(g_h[(size_t)u*32 + lane]*sc + shf, 0.f);
    for (int k = 0; k < NK; k++){
        if (g_hist[NK + k] == 0) continue;
        float p = 0.f, q = 0.f;
        for (int i = 0; i < Hh; i++){
            float xv = __shfl_sync(FULL, xv_l, i);
            p = fmaf(xv, __ldg(g_A1 + k*Hh*Hh + i*Hh + lane), p);
            q = fmaf(xv, __ldg(g_B1 + k*Hh*Hh + i*Hh + lane), q);
        }
        size_t ro = ((size_t)(k*Nn + u))*64;
        g_PQ[ro + lane] = p;
        g_PQ[ro + 32 + lane] = q;
    }
}

// ==== aggregation: warp/node. Fast path: pipelined dual-stream raw-x gather + factorized A/B.
//      General path: gather P/Q rows. BN+ReLU inline on inputs for LAYER==1. ====
template<int DIN, int LAYER>
__global__ void __launch_bounds__(256)
k_agg(const float* __restrict__ xin, const float* __restrict__ root,
      const float* __restrict__ bias, const float* __restrict__ gamma0,
      const float* __restrict__ beta0, float* __restrict__ hout){
    constexpr int NC = DIN/4;        // float4 chunks per x row
    constexpr int NS = 32/NC;        // edge slots per stream
    __shared__ float sA[DIN*32], sB[DIN*32], sR[DIN*32];
    __shared__ float sScale[32], sShift[32];
    __shared__ float sAcc[8][2*DIN];
    __shared__ float ss[32], sq[32];
    int t = threadIdx.x, lane = t & 31, w = t >> 5;
    int nlive = g_nlive[LAYER];
    int kl = g_klive[LAYER];
    if (t < 32){ ss[t] = 0.f; sq[t] = 0.f; }
    if (LAYER == 1 && t < 32){
        float mu  = g_stats[t]    * (1.f/(float)Nn);
        float var = g_stats[32+t] * (1.f/(float)Nn) - mu*mu;
        float sc  = rsqrtf(var + EPSI) * __ldg(gamma0+t);
        sScale[t] = sc;
        sShift[t] = __ldg(beta0+t) - mu*sc;
    }
    for (int d = t; d < DIN*32; d += 256) sR[d] = __ldg(root + d);
    if (nlive == 1){
        const float* A = LAYER ? g_A1 : g_A0;
        const float* B = LAYER ? g_B1 : g_B0;
        for (int d = t; d < DIN*32; d += 256){
            sA[d] = __ldg(A + kl*DIN*32 + d);
            sB[d] = __ldg(B + kl*DIN*32 + d);
        }
    }
    __syncthreads();

    int v = blockIdx.x*8 + w;                 // grid exact: 2500*8 = Nn
    int s = g_off[v], e1 = g_end[v];
    float msg;
    if (nlive == 1){
        // ---------- fast path: two pipelined streams, 2*NS edges in flight ----------
        int slot = lane / NC, c = lane % NC;
        const float4* x4 = (const float4*)xin;
        float4 ya0={0,0,0,0}, yb0={0,0,0,0}, ya1={0,0,0,0}, yb1={0,0,0,0};
        int i0 = s + slot, i1 = i0 + NS;
        bool v0 = i0 < e1, v1 = i1 < e1;
        uint2 p0, p1;
        if (v0) p0 = g_ebuf[i0];
        if (v1) p1 = g_ebuf[i1];
        while (__any_sync(FULL, v0)){
            int n0 = i0 + 2*NS, n1 = i1 + 2*NS;
            bool w0 = n0 < e1, w1 = n1 < e1;
            uint2 q0, q1;
            if (w0) q0 = g_ebuf[n0];       // prefetch next payloads
            if (w1) q1 = g_ebuf[n1];
            if (v0){
                int u = p0.x & 0xFFFF; float a = __uint_as_float(p0.y);
                float4 xc = x4[(size_t)u*NC + c];
                if (LAYER == 1){
                    int f = c*4;
                    xc.x = fmaxf(xc.x*sScale[f+0] + sShift[f+0], 0.f);
                    xc.y = fmaxf(xc.y*sScale[f+1] + sShift[f+1], 0.f);
                    xc.z = fmaxf(xc.z*sScale[f+2] + sShift[f+2], 0.f);
                    xc.w = fmaxf(xc.w*sScale[f+3] + sShift[f+3], 0.f);
                }
                ya0.x = fmaf(a, xc.x, ya0.x); yb0.x += xc.x;
                ya0.y = fmaf(a, xc.y, ya0.y); yb0.y += xc.y;
                ya0.z = fmaf(a, xc.z, ya0.z); yb0.z += xc.z;
                ya0.w = fmaf(a, xc.w, ya0.w); yb0.w += xc.w;
            }
            if (v1){
                int u = p1.x & 0xFFFF; float a = __uint_as_float(p1.y);
                float4 xc = x4[(size_t)u*NC + c];
                if (LAYER == 1){
                    int f = c*4;
                    xc.x = fmaxf(xc.x*sScale[f+0] + sShift[f+0], 0.f);
                    xc.y = fmaxf(xc.y*sScale[f+1] + sShift[f+1], 0.f);
                    xc.z = fmaxf(xc.z*sScale[f+2] + sShift[f+2], 0.f);
                    xc.w = fmaxf(xc.w*sScale[f+3] + sShift[f+3], 0.f);
                }
                ya1.x = fmaf(a, xc.x, ya1.x); yb1.x += xc.x;
                ya1.y = fmaf(a, xc.y, ya1.y); yb1.y += xc.y;
                ya1.z = fmaf(a, xc.z, ya1.z); yb1.z += xc.z;
                ya1.w = fmaf(a, xc.w, ya1.w); yb1.w += xc.w;
            }
            i0 = n0; i1 = n1; v0 = w0; v1 = w1; p0 = q0; p1 = q1;
        }
        float4 ya, yb;
        ya.x = ya0.x + ya1.x; ya.y = ya0.y + ya1.y;
        ya.z = ya0.z + ya1.z; ya.w = ya0.w + ya1.w;
        yb.x = yb0.x + yb1.x; yb.y = yb0.y + yb1.y;
        yb.z = yb0.z + yb1.z; yb.w = yb0.w + yb1.w;
        #pragma unroll
        for (int off = NC; off < 32; off <<= 1){
            ya.x += __shfl_xor_sync(FULL, ya.x, off);
            ya.y += __shfl_xor_sync(FULL, ya.y, off);
            ya.z += __shfl_xor_sync(FULL, ya.z, off);
            ya.w += __shfl_xor_sync(FULL, ya.w, off);
            yb.x += __shfl_xor_sync(FULL, yb.x, off);
            yb.y += __shfl_xor_sync(FULL, yb.y, off);
            yb.z += __shfl_xor_sync(FULL, yb.z, off);
            yb.w += __shfl_xor_sync(FULL, yb.w, off);
        }
        if (lane < NC){
            int f = lane*4;
            sAcc[w][f+0] = ya.x; sAcc[w][f+1] = ya.y;
            sAcc[w][f+2] = ya.z; sAcc[w][f+3] = ya.w;
            sAcc[w][DIN+f+0] = yb.x; sAcc[w][DIN+f+1] = yb.y;
            sAcc[w][DIN+f+2] = yb.z; sAcc[w][DIN+f+3] = yb.w;
        }
        __syncwarp();
        msg = 0.f;
        #pragma unroll
        for (int i = 0; i < DIN; i++){
            msg = fmaf(sAcc[w][i],     sA[i*32+lane], msg);
            msg = fmaf(sAcc[w][DIN+i], sB[i*32+lane], msg);
        }
    } else {
        // ---------- general path: gather P/Q rows ----------
        int shift = 16 + (LAYER << 3);
        int slot = lane >> 3, c = lane & 7;
        float4 acc = {0,0,0,0};
        for (int base = s; base < e1; base += 4){
            int i = base + slot;
            if (i < e1){
                uint2 pl = g_ebuf[i];
                int u = pl.x & 0xFFFF; int kk = (pl.x >> shift) & 0xFF;
                float a = __uint_as_float(pl.y);
                const float4* row = (const float4*)(g_PQ + ((size_t)(kk*Nn + u))*64);
                float4 p = row[c], q = row[8+c];
                acc.x = fmaf(a, p.x, acc.x) + q.x;
                acc.y = fmaf(a, p.y, acc.y) + q.y;
                acc.z = fmaf(a, p.z, acc.z) + q.z;
                acc.w = fmaf(a, p.w, acc.w) + q.w;
            }
        }
        #pragma unroll
        for (int off = 8; off < 32; off <<= 1){
            acc.x += __shfl_xor_sync(FULL, acc.x, off);
            acc.y += __shfl_xor_sync(FULL, acc.y, off);
            acc.z += __shfl_xor_sync(FULL, acc.z, off);
            acc.w += __shfl_xor_sync(FULL, acc.w, off);
        }
        if (lane < 8){
            int f = lane*4;
            sAcc[w][f+0] = acc.x; sAcc[w][f+1] = acc.y;
            sAcc[w][f+2] = acc.z; sAcc[w][f+3] = acc.w;
        }
        __syncwarp();
        msg = sAcc[w][lane];
    }

    // ---------- common epilogue ----------
    float inv = 1.f / fmaxf((float)(e1 - s), 1.f);
    float xv = 0.f;
    if (lane < DIN){
        xv = __ldg(xin + (size_t)v*DIN + lane);
        if (LAYER == 1) xv = fmaxf(xv*sScale[lane] + sShift[lane], 0.f);
    }
    float rt = 0.f;
    #pragma unroll
    for (int i = 0; i < DIN; i++)
        rt = fmaf(__shfl_sync(FULL, xv, i), sR[i*32+lane], rt);
    float o = rt + msg*inv + __ldg(bias+lane);
    hout[(size_t)v*32 + lane] = o;
    atomicAdd(&ss[lane], o);
    atomicAdd(&sq[lane], o*o);
    __syncthreads();
    if (t < 32){
        atomicAdd(&g_stats[LAYER*64 + t],      ss[t]);
        atomicAdd(&g_stats[LAYER*64 + 32 + t], sq[t]);
    }
}

// ==== BN2 + ReLU + pooling (layer-1 stats) ====
__global__ void __launch_bounds__(256)
k_apply1(const float* h2, const float* gamma, const float* beta, const int* batch){
    int idx = blockIdx.x*blockDim.x + threadIdx.x;
    if (idx >= Nn*Hh) return;
    int f = idx & 31, v = idx >> 5;
    float mu  = g_stats[64+f] * (1.f/(float)Nn);
    float var = g_stats[96+f] * (1.f/(float)Nn) - mu*mu;
    float sc  = rsqrtf(var + EPSI) * __ldg(gamma+f);
    float xv = fmaxf((h2[idx] - mu)*sc + __ldg(beta+f), 0.f);
    int g = batch[v];
    atomicAdd(&g_pool[g*Hh + f], xv);
    if (f == 0) atomicAdd(&g_pcnt[g], 1);
}

// ==== readout MLP; self-cleans g_hist + g_total ====
__global__ void __launch_bounds__(64)
k_mlp(const float* edft, const float* w1, const float* b1,
      const float* w2, const float* b2, float* out){
    int g = threadIdx.x;
    g_hist[g] = 0;
    if (g < 2*NK - 64) g_hist[64 + g] = 0;
    if (g == 0) g_total = 0;
    if (g >= Gg) return;
    float zin[Hh+1];
    float inv = 1.f / fmaxf((float)g_pcnt[g], 1.f);
    for (int i = 0; i < Hh; i++) zin[i] = g_pool[g*Hh+i]*inv;
    zin[Hh] = edft[g];
    float o = b2[0];
    for (int j = 0; j < 64; j++){
        float hsum = b1[j];
        #pragma unroll
        for (int i = 0; i < Hh+1; i++) hsum = fmaf(zin[i], w1[i*64+j], hsum);
        o = fmaf(fmaxf(hsum, 0.f), w2[j], o);
    }
    out[g] = o;
}

extern "C" void kernel_launch(void* const* d_in, const int* in_sizes, int n_in,
                              void* d_out, int out_size){
    const float* x     = (const float*)d_in[0];
    const float* attr  = (const float*)d_in[1];
    const float* edft  = (const float*)d_in[2];
    const int*   src   = (const int*)  d_in[3];
    const int*   dst   = (const int*)  d_in[4];
    const int*   batch = (const int*)  d_in[5];
    const float* l0w1=(const float*)d_in[6],  *l0b1=(const float*)d_in[7];
    const float* l0w2=(const float*)d_in[8],  *l0b2=(const float*)d_in[9];
    const float* l0root=(const float*)d_in[10],*l0bias=(const float*)d_in[11];
    const float* l0g=(const float*)d_in[12],  *l0be=(const float*)d_in[13];
    const float* l1w1=(const float*)d_in[14], *l1b1=(const float*)d_in[15];
    const float* l1w2=(const float*)d_in[16], *l1b2=(const float*)d_in[17];
    const float* l1root=(const float*)d_in[18],*l1bias=(const float*)d_in[19];
    const float* l1g=(const float*)d_in[20],  *l1be=(const float*)d_in[21];
    const float* mw1=(const float*)d_in[22],  *mb1=(const float*)d_in[23];
    const float* mw2=(const float*)d_in[24],  *mb2=(const float*)d_in[25];
    float* out = (float*)d_out;

    void *pH, *pHn;
    cudaGetSymbolAddress(&pH,  g_h);
    cudaGetSymbolAddress(&pHn, g_hn);
    float* h  = (float*)pH;
    float* h2 = (float*)pHn;

    k_pre<<<2*NK + EDGE_BLKS, 256>>>(attr, dst,
                                     l0w1,l0b1,l0w2,l0b2, l1w1,l1b1,l1w2,l1b2);
    k_alloc<<<(Nn+255)/256,256>>>();
    k_fillPQ<<<EDGE_BLKS + AGG_BLKS, 256>>>(dst, src, attr, x);

    k_agg<D0,0><<<AGG_BLKS,256>>>(x, l0root, l0bias, l0g, l0be, h);
    k_PQ1<<<AGG_BLKS,256>>>(l0g, l0be);
    k_agg<Hh,1><<<AGG_BLKS,256>>>(h, l1root, l1bias, l0g, l0be, h2);
    k_apply1<<<(Nn*Hh+255)/256,256>>>(h2, l1g, l1be, batch);
    k_mlp<<<1,64>>>(edft, mw1, mb1, mw2, mb2, out);
}

// round 8
// speedup vs baseline: 2.5641x; 1.0133x over previous
#include <cuda_runtime.h>
#include <cfloat>

#define Nn 20000
#define Ee 320000
#define Gg 64
#define D0 16
#define Hh 32
#define NK 33
#define EPSI 1e-5f
#define FULL 0xffffffffu
#define EDGE_BLKS ((Ee+255)/256)      /* 1250 */
#define AGG_BLKS  (Nn/8)              /* 2500 (general-path PQ grids) */
#define AGG_GRID  592                 /* persistent agg: 4 blocks/SM */

// ---------------- static device scratch (zero-init at load; self-cleaning across replays) ----------------
__device__ float g_A0[NK*D0*Hh], g_B0[NK*D0*Hh];
__device__ float g_A1[NK*Hh*Hh], g_B1[NK*Hh*Hh];
__device__ unsigned char g_k0[Ee], g_k1[Ee];
__device__ int g_hist[2*NK];            // zeroed by k_mlp each run
__device__ int g_deg[Nn];               // zeroed by k_alloc after read
__device__ int g_total;                 // zeroed by k_mlp each run
__device__ int g_off[Nn], g_end[Nn], g_cur[Nn];
__device__ int g_nlive[2], g_klive[2];
__device__ uint2 g_ebuf[Ee];            // CSR-ordered packed payload
__device__ __align__(16) float g_PQ[(size_t)NK*Nn*64];   // general path only
__device__ __align__(16) float g_h[Nn*Hh], g_hn[Nn*Hh];
__device__ float g_stats[4*Hh];         // [sum0|sq0|sum1|sq1], zeroed by k_pre block 0
__device__ float g_pool[Gg*Hh];
__device__ int   g_pcnt[Gg];

__device__ __forceinline__ void rank32(float wj, float bj, float& t, int& r, int j){
    t = (wj != 0.0f) ? (-bj / wj) : FLT_MAX;
    r = 0;
    #pragma unroll
    for (int m = 0; m < 32; m++){
        float tm = __shfl_sync(FULL, t, m);
        r += (tm < t || (tm == t && m < j));
    }
}

// ==== fused: blocks [0,2*NK) buildAB, blocks [2*NK,...) per-edge interval/hist/deg ====
__global__ void __launch_bounds__(256)
k_pre(const float* attr, const int* dst,
      const float* ew1a, const float* eb1a, const float* ew2a, const float* eb2a,
      const float* ew1b, const float* eb1b, const float* ew2b, const float* eb2b){
    int t = threadIdx.x;
    if (blockIdx.x < 2*NK){
        if (blockIdx.x == 0){
            for (int i = t; i < 4*Hh; i += 256) g_stats[i] = 0.f;
            for (int i = t; i < Gg*Hh; i += 256) g_pool[i] = 0.f;
            if (t < Gg) g_pcnt[t] = 0;
        }
        int layer = (blockIdx.x >= NK);
        int k = blockIdx.x - layer*NK;
        int D = layer ? (Hh*Hh) : (D0*Hh);
        float* A = layer ? g_A1 : g_A0;
        float* B = layer ? g_B1 : g_B0;
        const float* ew1 = layer ? ew1b : ew1a;
        const float* eb1 = layer ? eb1b : eb1a;
        const float* ew2 = layer ? ew2b : ew2a;
        const float* eb2 = layer ? eb2b : eb2a;
        __shared__ float sw[32], sb[32]; __shared__ int sr[32];
        if (t < 32){
            float wj = ew1[t], bj = eb1[t], tv; int r;
            rank32(wj, bj, tv, r, t);
            sw[t]=wj; sb[t]=bj; sr[t]=r;
        }
        __syncthreads();
        for (int d = t; d < D; d += 256){
            float a = 0.f, b = eb2[d];
            for (int j=0;j<32;j++){
                float wj = sw[j];
                bool act = (wj > 0.f) ? (k > sr[j]) : ((wj < 0.f) ? (k <= sr[j]) : (sb[j] > 0.f));
                if (act){ float w2 = ew2[j*D+d]; a += wj*w2; b += sb[j]*w2; }
            }
            A[k*D+d]=a; B[k*D+d]=b;
        }
        return;
    }
    // ---- edge role ----
    __shared__ float st0[32], st1[32];
    __shared__ int sh[2*NK];
    int lane = t & 31;
    if (t < 32){ float tv; int r; rank32(ew1a[t], eb1a[t], tv, r, t); st0[r]=tv; }
    else if (t < 64){ int j=t-32; float tv; int r; rank32(ew1b[j], eb1b[j], tv, r, j); st1[r]=tv; }
    if (t < 2*NK) sh[t] = 0;
    __syncthreads();
    int e = (blockIdx.x - 2*NK)*256 + t;
    bool valid = (e < Ee);
    float a = valid ? attr[e] : -FLT_MAX;
    int k0 = 0, k1 = 0;
    #pragma unroll
    for (int step = 16; step > 0; step >>= 1){
        if (st0[k0 + step - 1] <= a) k0 += step;
        if (st1[k1 + step - 1] <= a) k1 += step;
    }
    k0 += (st0[k0] <= a);   // counts range [0,32]
    k1 += (st1[k1] <= a);
    if (valid){
        g_k0[e]=(unsigned char)k0; g_k1[e]=(unsigned char)k1;
        atomicAdd(&g_deg[dst[e]],1);
    }
    int key0 = valid ? k0 : -1;
    unsigned m0 = __match_any_sync(FULL, key0);
    if (valid && lane == (__ffs(m0)-1)) atomicAdd(&sh[k0], __popc(m0));
    int key1 = valid ? k1 : -1;
    unsigned m1 = __match_any_sync(FULL, key1);
    if (valid && lane == (__ffs(m1)-1)) atomicAdd(&sh[NK+k1], __popc(m1));
    __syncthreads();
    if (t < 2*NK && sh[t]) atomicAdd(&g_hist[t], sh[t]);
}

// ==== segment allocation: warp-aggregated atomic bump; order-free CSR. Also nlive detect. ====
__global__ void __launch_bounds__(256)
k_alloc(){
    int i = blockIdx.x*256 + threadIdx.x;
    int lane = threadIdx.x & 31;
    if (blockIdx.x == 0 && threadIdx.x < 2){
        int base = threadIdx.x*NK, n = 0, kl = 0;
        for (int k = 0; k < NK; k++) if (g_hist[base+k] > 0){ n++; kl = k; }
        g_nlive[threadIdx.x] = n; g_klive[threadIdx.x] = kl;
    }
    int d = (i < Nn) ? g_deg[i] : 0;
    int sc = d;
    #pragma unroll
    for (int off = 1; off < 32; off <<= 1){
        int y = __shfl_up_sync(FULL, sc, off);
        if (lane >= off) sc += y;
    }
    int tot = __shfl_sync(FULL, sc, 31);
    int base = 0;
    if (lane == 31 && tot) base = atomicAdd(&g_total, tot);
    base = __shfl_sync(FULL, base, 31);
    if (i < Nn){
        int my = base + sc - d;
        g_off[i] = my; g_cur[i] = my; g_end[i] = my + d;
        g_deg[i] = 0;
    }
}

// ==== fused: blocks [0,EDGE_BLKS) CSR fill; blocks [EDGE_BLKS,..) PQ layer 0 (general only) ====
__global__ void __launch_bounds__(256)
k_fillPQ(const int* dst, const int* src, const float* attr, const float* xin){
    if (blockIdx.x < EDGE_BLKS){
        bool fastboth = (g_nlive[0] == 1) & (g_nlive[1] == 1);
        int e = blockIdx.x*256 + threadIdx.x;
        if (e < Ee){
            unsigned px = (unsigned)src[e];
            if (!fastboth)
                px |= ((unsigned)g_k0[e] << 16) | ((unsigned)g_k1[e] << 24);
            uint2 pl; pl.x = px; pl.y = __float_as_uint(attr[e]);
            int p = atomicAdd(&g_cur[dst[e]], 1);
            g_ebuf[p] = pl;
        }
        return;
    }
    if (g_nlive[0] == 1) return;     // fast path: PQ not needed
    int lane = threadIdx.x & 31;
    int u = (blockIdx.x - EDGE_BLKS)*8 + (threadIdx.x >> 5);
    if (u >= Nn) return;
    float xv_l = (lane < D0) ? __ldg(xin + (size_t)u*D0 + lane) : 0.f;
    for (int k = 0; k < NK; k++){
        if (g_hist[k] == 0) continue;
        float p = 0.f, q = 0.f;
        for (int i = 0; i < D0; i++){
            float xv = __shfl_sync(FULL, xv_l, i);
            p = fmaf(xv, __ldg(g_A0 + k*D0*Hh + i*Hh + lane), p);
            q = fmaf(xv, __ldg(g_B0 + k*D0*Hh + i*Hh + lane), q);
        }
        size_t ro = ((size_t)(k*Nn + u))*64;
        g_PQ[ro + lane] = p;
        g_PQ[ro + 32 + lane] = q;
    }
}

// ==== PQ layer 1 (general path only; BN+ReLU inline from layer-0 stats) ====
__global__ void __launch_bounds__(256)
k_PQ1(const float* gamma, const float* beta){
    if (g_nlive[1] == 1) return;
    int lane = threadIdx.x & 31;
    int u = blockIdx.x*8 + (threadIdx.x >> 5);
    if (u >= Nn) return;
    float mu  = g_stats[lane]    * (1.f/(float)Nn);
    float var = g_stats[32+lane] * (1.f/(float)Nn) - mu*mu;
    float sc  = rsqrtf(var + EPSI) * __ldg(gamma+lane);
    float shf = __ldg(beta+lane) - mu*sc;
    float xv_l = fmaxf(g_h[(size_t)u*32 + lane]*sc + shf, 0.f);
    for (int k = 0; k < NK; k++){
        if (g_hist[NK + k] == 0) continue;
        float p = 0.f, q = 0.f;
        for (int i = 0; i < Hh; i++){
            float xv = __shfl_sync(FULL, xv_l, i);
            p = fmaf(xv, __ldg(g_A1 + k*Hh*Hh + i*Hh + lane), p);
            q = fmaf(xv, __ldg(g_B1 + k*Hh*Hh + i*Hh + lane), q);
        }
        size_t ro = ((size_t)(k*Nn + u))*64;
        g_PQ[ro + lane] = p;
        g_PQ[ro + 32 + lane] = q;
    }
}

// ==== PERSISTENT aggregation: 592 blocks; each block loads smem once, warps stride nodes ====
template<int DIN, int LAYER>
__global__ void __launch_bounds__(256)
k_agg(const float* __restrict__ xin, const float* __restrict__ root,
      const float* __restrict__ bias, const float* __restrict__ gamma0,
      const float* __restrict__ beta0, float* __restrict__ hout){
    constexpr int NC = DIN/4;        // float4 chunks per x row
    constexpr int NS = 32/NC;        // edge slots per stream
    __shared__ float sA[DIN*32], sB[DIN*32], sR[DIN*32];
    __shared__ float sScale[32], sShift[32], sBias[32];
    __shared__ float sAcc[8][2*DIN];
    __shared__ float ss[32], sq[32];
    int t = threadIdx.x, lane = t & 31, w = t >> 5;
    int nlive = g_nlive[LAYER];
    int kl = g_klive[LAYER];
    if (t < 32){ ss[t] = 0.f; sq[t] = 0.f; sBias[t] = __ldg(bias+t); }
    if (LAYER == 1 && t < 32){
        float mu  = g_stats[t]    * (1.f/(float)Nn);
        float var = g_stats[32+t] * (1.f/(float)Nn) - mu*mu;
        float sc  = rsqrtf(var + EPSI) * __ldg(gamma0+t);
        sScale[t] = sc;
        sShift[t] = __ldg(beta0+t) - mu*sc;
    }
    for (int d = t; d < DIN*32; d += 256) sR[d] = __ldg(root + d);
    if (nlive == 1){
        const float* A = LAYER ? g_A1 : g_A0;
        const float* B = LAYER ? g_B1 : g_B0;
        for (int d = t; d < DIN*32; d += 256){
            sA[d] = __ldg(A + kl*DIN*32 + d);
            sB[d] = __ldg(B + kl*DIN*32 + d);
        }
    }
    __syncthreads();

    int slot, c;
    if (nlive == 1){ slot = lane / NC; c = lane % NC; }
    else           { slot = lane >> 3; c = lane & 7; }
    const float4* x4 = (const float4*)xin;

    for (int v = blockIdx.x*8 + w; v < Nn; v += AGG_GRID*8){
        int s = g_off[v], e1 = g_end[v];
        float msg;
        if (nlive == 1){
            // ---------- fast path: two pipelined streams, 2*NS edges in flight ----------
            float4 ya0={0,0,0,0}, yb0={0,0,0,0}, ya1={0,0,0,0}, yb1={0,0,0,0};
            int i0 = s + slot, i1 = i0 + NS;
            bool v0 = i0 < e1, v1 = i1 < e1;
            uint2 p0, p1;
            if (v0) p0 = g_ebuf[i0];
            if (v1) p1 = g_ebuf[i1];
            while (__any_sync(FULL, v0)){
                int n0 = i0 + 2*NS, n1 = i1 + 2*NS;
                bool w0 = n0 < e1, w1 = n1 < e1;
                uint2 q0, q1;
                if (w0) q0 = g_ebuf[n0];
                if (w1) q1 = g_ebuf[n1];
                if (v0){
                    int u = p0.x & 0xFFFF; float a = __uint_as_float(p0.y);
                    float4 xc = x4[(size_t)u*NC + c];
                    if (LAYER == 1){
                        int f = c*4;
                        xc.x = fmaxf(xc.x*sScale[f+0] + sShift[f+0], 0.f);
                        xc.y = fmaxf(xc.y*sScale[f+1] + sShift[f+1], 0.f);
                        xc.z = fmaxf(xc.z*sScale[f+2] + sShift[f+2], 0.f);
                        xc.w = fmaxf(xc.w*sScale[f+3] + sShift[f+3], 0.f);
                    }
                    ya0.x = fmaf(a, xc.x, ya0.x); yb0.x += xc.x;
                    ya0.y = fmaf(a, xc.y, ya0.y); yb0.y += xc.y;
                    ya0.z = fmaf(a, xc.z, ya0.z); yb0.z += xc.z;
                    ya0.w = fmaf(a, xc.w, ya0.w); yb0.w += xc.w;
                }
                if (v1){
                    int u = p1.x & 0xFFFF; float a = __uint_as_float(p1.y);
                    float4 xc = x4[(size_t)u*NC + c];
                    if (LAYER == 1){
                        int f = c*4;
                        xc.x = fmaxf(xc.x*sScale[f+0] + sShift[f+0], 0.f);
                        xc.y = fmaxf(xc.y*sScale[f+1] + sShift[f+1], 0.f);
                        xc.z = fmaxf(xc.z*sScale[f+2] + sShift[f+2], 0.f);
                        xc.w = fmaxf(xc.w*sScale[f+3] + sShift[f+3], 0.f);
                    }
                    ya1.x = fmaf(a, xc.x, ya1.x); yb1.x += xc.x;
                    ya1.y = fmaf(a, xc.y, ya1.y); yb1.y += xc.y;
                    ya1.z = fmaf(a, xc.z, ya1.z); yb1.z += xc.z;
                    ya1.w = fmaf(a, xc.w, ya1.w); yb1.w += xc.w;
                }
                i0 = n0; i1 = n1; v0 = w0; v1 = w1; p0 = q0; p1 = q1;
            }
            float4 ya, yb;
            ya.x = ya0.x + ya1.x; ya.y = ya0.y + ya1.y;
            ya.z = ya0.z + ya1.z; ya.w = ya0.w + ya1.w;
            yb.x = yb0.x + yb1.x; yb.y = yb0.y + yb1.y;
            yb.z = yb0.z + yb1.z; yb.w = yb0.w + yb1.w;
            #pragma unroll
            for (int off = NC; off < 32; off <<= 1){
                ya.x += __shfl_xor_sync(FULL, ya.x, off);
                ya.y += __shfl_xor_sync(FULL, ya.y, off);
                ya.z += __shfl_xor_sync(FULL, ya.z, off);
                ya.w += __shfl_xor_sync(FULL, ya.w, off);
                yb.x += __shfl_xor_sync(FULL, yb.x, off);
                yb.y += __shfl_xor_sync(FULL, yb.y, off);
                yb.z += __shfl_xor_sync(FULL, yb.z, off);
                yb.w += __shfl_xor_sync(FULL, yb.w, off);
            }
            if (lane < NC){
                int f = lane*4;
                sAcc[w][f+0] = ya.x; sAcc[w][f+1] = ya.y;
                sAcc[w][f+2] = ya.z; sAcc[w][f+3] = ya.w;
                sAcc[w][DIN+f+0] = yb.x; sAcc[w][DIN+f+1] = yb.y;
                sAcc[w][DIN+f+2] = yb.z; sAcc[w][DIN+f+3] = yb.w;
            }
            __syncwarp();
            msg = 0.f;
            #pragma unroll
            for (int i = 0; i < DIN; i++){
                msg = fmaf(sAcc[w][i],     sA[i*32+lane], msg);
                msg = fmaf(sAcc[w][DIN+i], sB[i*32+lane], msg);
            }
        } else {
            // ---------- general path: gather P/Q rows ----------
            int shift = 16 + (LAYER << 3);
            float4 acc = {0,0,0,0};
            for (int base = s; base < e1; base += 4){
                int i = base + slot;
                if (i < e1){
                    uint2 pl = g_ebuf[i];
                    int u = pl.x & 0xFFFF; int kk = (pl.x >> shift) & 0xFF;
                    float a = __uint_as_float(pl.y);
                    const float4* row = (const float4*)(g_PQ + ((size_t)(kk*Nn + u))*64);
                    float4 p = row[c], q = row[8+c];
                    acc.x = fmaf(a, p.x, acc.x) + q.x;
                    acc.y = fmaf(a, p.y, acc.y) + q.y;
                    acc.z = fmaf(a, p.z, acc.z) + q.z;
                    acc.w = fmaf(a, p.w, acc.w) + q.w;
                }
            }
            #pragma unroll
            for (int off = 8; off < 32; off <<= 1){
                acc.x += __shfl_xor_sync(FULL, acc.x, off);
                acc.y += __shfl_xor_sync(FULL, acc.y, off);
                acc.z += __shfl_xor_sync(FULL, acc.z, off);
                acc.w += __shfl_xor_sync(FULL, acc.w, off);
            }
            if (lane < 8){
                int f = lane*4;
                sAcc[w][f+0] = acc.x; sAcc[w][f+1] = acc.y;
                sAcc[w][f+2] = acc.z; sAcc[w][f+3] = acc.w;
            }
            __syncwarp();
            msg = sAcc[w][lane];
        }

        // ---------- epilogue for this node ----------
        float inv = 1.f / fmaxf((float)(e1 - s), 1.f);
        float xv = 0.f;
        if (lane < DIN){
            xv = __ldg(xin + (size_t)v*DIN + lane);
            if (LAYER == 1) xv = fmaxf(xv*sScale[lane] + sShift[lane], 0.f);
        }
        float rt = 0.f;
        #pragma unroll
        for (int i = 0; i < DIN; i++)
            rt = fmaf(__shfl_sync(FULL, xv, i), sR[i*32+lane], rt);
        float o = rt + msg*inv + sBias[lane];
        hout[(size_t)v*32 + lane] = o;
        atomicAdd(&ss[lane], o);
        atomicAdd(&sq[lane], o*o);
        __syncwarp();
    }
    __syncthreads();
    if (t < 32){
        atomicAdd(&g_stats[LAYER*64 + t],      ss[t]);
        atomicAdd(&g_stats[LAYER*64 + 32 + t], sq[t]);
    }
}

// ==== BN2 + ReLU + pooling (layer-1 stats) ====
__global__ void __launch_bounds__(256)
k_apply1(const float* h2, const float* gamma, const float* beta, const int* batch){
    int idx = blockIdx.x*blockDim.x + threadIdx.x;
    if (idx >= Nn*Hh) return;
    int f = idx & 31, v = idx >> 5;
    float mu  = g_stats[64+f] * (1.f/(float)Nn);
    float var = g_stats[96+f] * (1.f/(float)Nn) - mu*mu;
    float sc  = rsqrtf(var + EPSI) * __ldg(gamma+f);
    float xv = fmaxf((h2[idx] - mu)*sc + __ldg(beta+f), 0.f);
    int g = batch[v];
    atomicAdd(&g_pool[g*Hh + f], xv);
    if (f == 0) atomicAdd(&g_pcnt[g], 1);
}

// ==== readout MLP; self-cleans g_hist + g_total ====
__global__ void __launch_bounds__(64)
k_mlp(const float* edft, const float* w1, const float* b1,
      const float* w2, const float* b2, float* out){
    int g = threadIdx.x;
    g_hist[g] = 0;
    if (g < 2*NK - 64) g_hist[64 + g] = 0;
    if (g == 0) g_total = 0;
    if (g >= Gg) return;
    float zin[Hh+1];
    float inv = 1.f / fmaxf((float)g_pcnt[g], 1.f);
    for (int i = 0; i < Hh; i++) zin[i] = g_pool[g*Hh+i]*inv;
    zin[Hh] = edft[g];
    float o = b2[0];
    for (int j = 0; j < 64; j++){
        float hsum = b1[j];
        #pragma unroll
        for (int i = 0; i < Hh+1; i++) hsum = fmaf(zin[i], w1[i*64+j], hsum);
        o = fmaf(fmaxf(hsum, 0.f), w2[j], o);
    }
    out[g] = o;
}

extern "C" void kernel_launch(void* const* d_in, const int* in_sizes, int n_in,
                              void* d_out, int out_size){
    const float* x     = (const float*)d_in[0];
    const float* attr  = (const float*)d_in[1];
    const float* edft  = (const float*)d_in[2];
    const int*   src   = (const int*)  d_in[3];
    const int*   dst   = (const int*)  d_in[4];
    const int*   batch = (const int*)  d_in[5];
    const float* l0w1=(const float*)d_in[6],  *l0b1=(const float*)d_in[7];
    const float* l0w2=(const float*)d_in[8],  *l0b2=(const float*)d_in[9];
    const float* l0root=(const float*)d_in[10],*l0bias=(const float*)d_in[11];
    const float* l0g=(const float*)d_in[12],  *l0be=(const float*)d_in[13];
    const float* l1w1=(const float*)d_in[14], *l1b1=(const float*)d_in[15];
    const float* l1w2=(const float*)d_in[16], *l1b2=(const float*)d_in[17];
    const float* l1root=(const float*)d_in[18],*l1bias=(const float*)d_in[19];
    const float* l1g=(const float*)d_in[20],  *l1be=(const float*)d_in[21];
    const float* mw1=(const float*)d_in[22],  *mb1=(const float*)d_in[23];
    const float* mw2=(const float*)d_in[24],  *mb2=(const float*)d_in[25];
    float* out = (float*)d_out;

    void *pH, *pHn;
    cudaGetSymbolAddress(&pH,  g_h);
    cudaGetSymbolAddress(&pHn, g_hn);
    float* h  = (float*)pH;
    float* h2 = (float*)pHn;

    k_pre<<<2*NK + EDGE_BLKS, 256>>>(attr, dst,
                                     l0w1,l0b1,l0w2,l0b2, l1w1,l1b1,l1w2,l1b2);
    k_alloc<<<(Nn+255)/256,256>>>();
    k_fillPQ<<<EDGE_BLKS + AGG_BLKS, 256>>>(dst, src, attr, x);

    k_agg<D0,0><<<AGG_GRID,256>>>(x, l0root, l0bias, l0g, l0be, h);
    k_PQ1<<<AGG_BLKS,256>>>(l0g, l0be);
    k_agg<Hh,1><<<AGG_GRID,256>>>(h, l1root, l1bias, l0g, l0be, h2);
    k_apply1<<<(Nn*Hh+255)/256,256>>>(h2, l1g, l1be, batch);
    k_mlp<<<1,64>>>(edft, mw1, mb1, mw2, mb2, out);
}